// round 13
// baseline (speedup 1.0000x reference)
#include <cuda_runtime.h>
#include <cstdint>

#define NROWS  (1u << 20)
#define KTOP   1024
#define ECAP   8192
#define BIN0   0xBE80u
#define TOPBIN 0xBF7Fu
#define TILES  8
#define TROWS  32
#define GBLK   64u

// ---------------- scratch (module-load allocations, allowed) ----------------
__device__ unsigned            g_key[NROWS];
__device__ unsigned            g_cntT, g_ticket;
__device__ unsigned            g_sync1;
__device__ unsigned            g_gdone[16];
__device__ uint2               g_T[ECAP];
__device__ uint2               g_A[KTOP];
__device__ uint2               g_E2[ECAP];
__device__ unsigned            g_order[KTOP];
__device__ float4              g_boxes[KTOP];
__device__ float4              g_info[KTOP];
__device__ unsigned            g_validw[32];
__device__ unsigned long long  g_rowNZ[16];
__device__ __align__(16) unsigned long long g_M[KTOP * 16];

// ---- release/acquire sync helpers (generic addr; unified address space) ----
__device__ __forceinline__ void sig_release(unsigned* p) {
    asm volatile("red.release.gpu.add.u32 [%0], 1;" :: "l"(p) : "memory");
}
__device__ __forceinline__ unsigned ld_acquire(unsigned* p) {
    unsigned v;
    asm volatile("ld.acquire.gpu.b32 %0, [%1];" : "=r"(v) : "l"(p) : "memory");
    return v;
}

// ---- single-warp suffix-scan boundary finder over 256 smem bins ------------
__device__ __forceinline__ void sufscan_find(const unsigned* hist, unsigned K,
                                             unsigned* outBin, unsigned* outK) {
    unsigned t = threadIdx.x;
    if (t < 32u) {
        unsigned h[8], s[8], acc = 0u;
        #pragma unroll
        for (int i = 7; i >= 0; i--) { h[i] = hist[t * 8u + (unsigned)i]; acc += h[i]; s[i] = acc; }
        unsigned suf = acc;
        #pragma unroll
        for (int off = 1; off < 32; off <<= 1) {
            unsigned v = __shfl_down_sync(0xFFFFFFFFu, suf, off);
            if (t + (unsigned)off < 32u) suf += v;
        }
        unsigned base = suf - acc;
        #pragma unroll
        for (int i = 0; i < 8; i++) {
            unsigned Sinc = s[i] + base, Sexc = Sinc - h[i];
            if (Sexc < K && Sinc >= K) { *outBin = t * 8u + (unsigned)i; *outK = K - Sexc; }
        }
    }
}

// ---------------- K1: score + top-bin candidates + tail selection -----------
__global__ void __launch_bounds__(256) k_score(const float* __restrict__ pred) {
    __shared__ float4 sbuf[2][TROWS * 85 / 4];          // 21760 B (aliased later)
    __shared__ unsigned hist[256];
    __shared__ unsigned eq[128];
    __shared__ unsigned sh_bin, sh_K, sh_cntG, sh_cntEq, sh_cA, sh_cE, sh_isLast;
    unsigned t = threadIdx.x;
    size_t blockRow0 = (size_t)blockIdx.x * (TILES * TROWS);
    const float4* gsrc = reinterpret_cast<const float4*>(pred)
                         + blockRow0 * 85 / 4;

    {
        float4* dst = sbuf[0];
        #pragma unroll
        for (int k = 0; k < 3; k++) {
            unsigned i = t + (unsigned)k * 256u;
            if (i < 680u) {
                unsigned sa = (unsigned)__cvta_generic_to_shared(dst + i);
                asm volatile("cp.async.cg.shared.global [%0], [%1], 16;\n"
                             :: "r"(sa), "l"(gsrc + i));
            }
        }
        asm volatile("cp.async.commit_group;\n");
    }

    unsigned row = t >> 3, seg = t & 7u;
    #pragma unroll
    for (int tile = 0; tile < TILES; tile++) {
        if (tile + 1 < TILES) {
            float4* dst = sbuf[(tile + 1) & 1];
            const float4* src = gsrc + (size_t)(tile + 1) * 680u;
            #pragma unroll
            for (int k = 0; k < 3; k++) {
                unsigned i = t + (unsigned)k * 256u;
                if (i < 680u) {
                    unsigned sa = (unsigned)__cvta_generic_to_shared(dst + i);
                    asm volatile("cp.async.cg.shared.global [%0], [%1], 16;\n"
                                 :: "r"(sa), "l"(src + i));
                }
            }
            asm volatile("cp.async.commit_group;\n");
            asm volatile("cp.async.wait_group 1;\n");
        } else {
            asm volatile("cp.async.wait_group 0;\n");
        }
        __syncthreads();

        const float* s = reinterpret_cast<const float*>(sbuf[tile & 1]);
        const float* r = s + row * 85u;
        unsigned best = __float_as_uint(r[5 + seg * 10]);
        #pragma unroll
        for (int j = 1; j < 10; j++)
            best = max(best, __float_as_uint(r[5 + seg * 10 + j]));
        #pragma unroll
        for (int d = 4; d; d >>= 1)
            best = max(best, __shfl_down_sync(0xFFFFFFFFu, best, d, 8));
        if (seg == 0u) {
            float obj = r[4];
            float conf = __fmul_rn(obj, __uint_as_float(best));
            unsigned key = (conf >= 0.25f) ? (__float_as_uint(obj) | 0x80000000u)
                                           : 0x31914AD7u;
            unsigned grow = (unsigned)(blockRow0 + (size_t)tile * TROWS + row);
            g_key[grow] = key;
            if ((key >> 16) == TOPBIN) {
                unsigned pn = atomicAdd(&g_cntT, 1u);
                if (pn < ECAP) g_T[pn] = make_uint2(key, grow);
            }
        }
        __syncthreads();
    }

    // ---- ticket: last block performs selection (kernel boundary = free sync) ----
    if (t == 0u) {
        unsigned old;
        asm volatile("atom.add.acq_rel.gpu.u32 %0, [%1], 1;"
                     : "=r"(old) : "l"(&g_ticket) : "memory");
        sh_isLast = (old == gridDim.x - 1u) ? 1u : 0u;
    }
    __syncthreads();
    if (!sh_isLast) return;

    // ================= phase S (256 threads, smem aliases sbuf) =============
    unsigned long long* pA = reinterpret_cast<unsigned long long*>(&sbuf[0][0]);
    unsigned cntT = g_cntT;
    bool fb = !(cntT >= KTOP && cntT <= (unsigned)ECAP);
    const uint2* src;
    unsigned CE, K2, b1v, cntA;

    if (!fb) {
        src = g_T; CE = cntT; K2 = KTOP; b1v = TOPBIN; cntA = 0u;
    } else {
        if (t == 0u) { sh_cA = 0u; sh_cE = 0u; }
        hist[t] = 0u;
        __syncthreads();
        const uint4* kp = reinterpret_cast<const uint4*>(g_key);
        for (unsigned i = t; i < NROWS / 4; i += 256u) {
            uint4 k4 = kp[i];
            unsigned b;
            b = (k4.x >> 16) - BIN0; if (b < 256u) atomicAdd(&hist[b], 1u);
            b = (k4.y >> 16) - BIN0; if (b < 256u) atomicAdd(&hist[b], 1u);
            b = (k4.z >> 16) - BIN0; if (b < 256u) atomicAdd(&hist[b], 1u);
            b = (k4.w >> 16) - BIN0; if (b < 256u) atomicAdd(&hist[b], 1u);
        }
        __syncthreads();
        sufscan_find(hist, KTOP, &sh_bin, &sh_K);
        __syncthreads();
        unsigned b1 = sh_bin + BIN0;
        unsigned Kb = sh_K;
        for (unsigned i = t; i < NROWS; i += 256u) {
            unsigned key = g_key[i];
            unsigned bin = key >> 16;
            if (bin > b1 && bin <= TOPBIN) {
                unsigned pn = atomicAdd(&sh_cA, 1u);
                if (pn < KTOP) g_A[pn] = make_uint2(key, i);
            } else if (bin == b1) {
                unsigned pn = atomicAdd(&sh_cE, 1u);
                if (pn < ECAP) g_E2[pn] = make_uint2(key, i);
            }
        }
        __syncthreads();
        src = g_E2; CE = min(sh_cE, (unsigned)ECAP);
        K2 = Kb; b1v = b1; cntA = min(sh_cA, (unsigned)KTOP);
    }

    // pass A: hist of key bits[8:16)
    hist[t] = 0u;
    if (t == 0u) { sh_cntG = 0u; sh_cntEq = 0u; }
    __syncthreads();
    for (unsigned e = t; e < CE; e += 256u)
        atomicAdd(&hist[(src[e].x >> 8) & 0xFFu], 1u);
    __syncthreads();
    sufscan_find(hist, K2, &sh_bin, &sh_K);
    __syncthreads();
    unsigned bh = sh_bin, K3 = sh_K;

    // pass B: hist of low 8 bits within sub-bin bh
    hist[t] = 0u;
    __syncthreads();
    for (unsigned e = t; e < CE; e += 256u) {
        unsigned k = src[e].x;
        if (((k >> 8) & 0xFFu) == bh) atomicAdd(&hist[k & 0xFFu], 1u);
    }
    __syncthreads();
    sufscan_find(hist, K3, &sh_bin, &sh_K);
    __syncthreads();
    unsigned VkLow = (bh << 8) | sh_bin;
    unsigned teq = sh_K;
    unsigned Vk  = (b1v << 16) | VkLow;

    // classify
    for (unsigned x = t; x < cntA; x += 256u) {
        uint2 a = g_A[x];
        pA[x] = ((unsigned long long)a.x << 32) | (unsigned)(~a.y);
    }
    for (unsigned e = t; e < CE; e += 256u) {
        uint2 v = src[e];
        unsigned low = v.x & 0xFFFFu;
        if (low > VkLow) {
            unsigned p = atomicAdd(&sh_cntG, 1u);
            pA[cntA + p] = ((unsigned long long)v.x << 32) | (unsigned)(~v.y);
        } else if (low == VkLow) {
            unsigned p = atomicAdd(&sh_cntEq, 1u);
            if (p < 128u) eq[p] = v.y;
        }
    }
    __syncthreads();
    unsigned cntG = sh_cntG, cntEq = min(sh_cntEq, 128u);

    // sort ties ascending by index
    if (cntEq <= 32u) {
        if (t < 32u) {
            unsigned val = (t < cntEq) ? eq[t] : 0xFFFFFFFFu;
            #pragma unroll
            for (unsigned kk = 2; kk <= 32; kk <<= 1)
                for (unsigned j = kk >> 1; j > 0; j >>= 1) {
                    unsigned other = __shfl_xor_sync(0xFFFFFFFFu, val, j);
                    bool up   = ((t & kk) == 0u);
                    bool lowp = ((t & j) == 0u);
                    unsigned mx = max(val, other), mn = min(val, other);
                    val = (lowp == up) ? mn : mx;
                }
            eq[t] = val;
        }
        __syncthreads();
    } else {
        if (t < 128u && t >= cntEq) eq[t] = 0xFFFFFFFFu;
        __syncthreads();
        for (unsigned kk = 2; kk <= 128; kk <<= 1)
            for (unsigned j = kk >> 1; j > 0; j >>= 1) {
                if (t < 128u) {
                    unsigned ixj = t ^ j;
                    if (ixj > t) {
                        unsigned a = eq[t], b = eq[ixj];
                        bool up = ((t & kk) == 0u);
                        if ((a > b) == up) { eq[t] = b; eq[ixj] = a; }
                    }
                }
                __syncthreads();
            }
    }
    for (unsigned x = t; x < teq; x += 256u)
        pA[cntA + cntG + x] = ((unsigned long long)Vk << 32) | (unsigned)(~eq[x]);
    __syncthreads();

    // bitonic 1024 descending by (key,~idx), 256 threads, in-place smem
    for (unsigned kk = 2; kk <= KTOP; kk <<= 1)
        for (unsigned j = kk >> 1; j > 0; j >>= 1) {
            for (unsigned x = t; x < KTOP; x += 256u) {
                unsigned ixj = x ^ j;
                if (ixj > x) {
                    unsigned long long a = pA[x], b = pA[ixj];
                    bool up = ((x & kk) == 0u);
                    if ((a < b) == up) { pA[x] = b; pA[ixj] = a; }
                }
            }
            __syncthreads();
        }

    for (unsigned x = t; x < KTOP; x += 256u) {
        unsigned long long val = pA[x];
        unsigned key = (unsigned)(val >> 32);
        unsigned idx = ~(unsigned)val;
        g_order[x] = idx;
        int valid = (key >= (BIN0 << 16)) ? 1 : 0;
        unsigned bal = __ballot_sync(0xFFFFFFFFu, valid);
        if ((x & 31u) == 0u) g_validw[x >> 5] = bal;
    }
}

// ---------------- K2: gather + IoU + pipelined NMS + output -----------------
__global__ void __launch_bounds__(1024) k_rest(const float* __restrict__ pred,
                                               float* __restrict__ out,
                                               int keepmode) {
    extern __shared__ __align__(16) unsigned long long Ms[];   // 1024*17 u64
    __shared__ float4 sb[KTOP];
    __shared__ unsigned long long keepw[16], remv[16], vmArr[16], tmpOr[32];
    __shared__ unsigned long long sh_nzg;
    unsigned t = threadIdx.x;
    unsigned bid = blockIdx.x;

    // ---- phase G: gather 16 slots per block ----
    if (t < 128u) {
        unsigned slot = bid * 16u + (t >> 3);
        unsigned seg = t & 7u;
        unsigned idx = g_order[slot];
        const float* r = pred + (size_t)idx * 85u;
        unsigned best = __float_as_uint(__ldg(r + 5 + seg * 10));
        unsigned bi   = seg * 10u;
        #pragma unroll
        for (int j = 1; j < 10; j++) {
            unsigned v = __float_as_uint(__ldg(r + 5 + seg * 10 + j));
            if (v > best) { best = v; bi = seg * 10u + (unsigned)j; }
        }
        #pragma unroll
        for (int d = 4; d; d >>= 1) {
            unsigned ob = __shfl_down_sync(0xFFFFFFFFu, best, d, 8);
            unsigned oi = __shfl_down_sync(0xFFFFFFFFu, bi, d, 8);
            if (ob > best || (ob == best && oi < bi)) { best = ob; bi = oi; }
        }
        if (seg == 0u) {
            float cx = __ldg(r), cy = __ldg(r + 1), w = __ldg(r + 2),
                  h = __ldg(r + 3), obj = __ldg(r + 4);
            float c = __uint_as_float(best);
            float hw = __fmul_rn(w, 0.5f), hh = __fmul_rn(h, 0.5f);
            g_boxes[slot] = make_float4(__fsub_rn(cx, hw), __fsub_rn(cy, hh),
                                        __fadd_rn(cx, hw), __fadd_rn(cy, hh));
            g_info[slot]  = make_float4(obj, c, (float)bi, 0.0f);
        }
    }
    __syncthreads();
    if (t == 0u) {
        sig_release(&g_sync1);
        while (ld_acquire(&g_sync1) < GBLK) __nanosleep(64);
    }
    __syncthreads();

    // ---- phase I: IoU; 4 threads per (row, word) ----
    sb[t] = g_boxes[t];
    __syncthreads();
    {
        unsigned unit = bid * 1024u + t;
        unsigned i   = unit >> 6;
        unsigned sub = unit & 63u;
        unsigned blk = sub >> 2;
        unsigned q   = sub & 3u;
        float4 bi = sb[i];
        float ai = __fmul_rn(__fsub_rn(bi.z, bi.x), __fsub_rn(bi.w, bi.y));
        unsigned long long bits = 0ull;
        unsigned jbase = blk * 64u + q * 16u;
        #pragma unroll
        for (int jj = 0; jj < 16; jj++) {
            float4 bj = sb[jbase + (unsigned)jj];
            float aj = __fmul_rn(__fsub_rn(bj.z, bj.x), __fsub_rn(bj.w, bj.y));
            float ltx = fmaxf(bi.x, bj.x), lty = fmaxf(bi.y, bj.y);
            float rbx = fminf(bi.z, bj.z), rby = fminf(bi.w, bj.w);
            float wx = fmaxf(__fsub_rn(rbx, ltx), 0.0f);
            float wy = fmaxf(__fsub_rn(rby, lty), 0.0f);
            float inter = __fmul_rn(wx, wy);
            float uni = __fsub_rn(__fadd_rn(ai, aj), inter);
            float iou = __fdiv_rn(inter, fmaxf(uni, 1e-9f));
            bits |= ((unsigned long long)(iou > 0.65f)) << (q * 16u + (unsigned)jj);
        }
        bits |= __shfl_xor_sync(0xFFFFFFFFu, bits, 1);
        bits |= __shfl_xor_sync(0xFFFFFFFFu, bits, 2);
        int nz = 0;
        if (q == 0u) {
            g_M[(size_t)i * 16 + blk] = bits;
            unsigned long long selfm = (blk == (i >> 6)) ? (1ull << (i & 63u)) : 0ull;
            nz = ((bits & ~selfm) != 0ull);
        }
        unsigned bal = __ballot_sync(0xFFFFFFFFu, nz);
        if ((t & 31u) == 0u && bal)
            atomicOr(&g_rowNZ[i >> 6], 1ull << (i & 63u));
    }
    __syncthreads();
    if (t == 0u) sig_release(&g_gdone[bid >> 2]);
    if (bid != 0u) return;

    // ---- phase N (block 0): pipelined stage + greedy NMS ----
    if (t < 16u) {
        remv[t] = 0ull;
        vmArr[t] = (unsigned long long)g_validw[2u * t]
                 | ((unsigned long long)g_validw[2u * t + 1u] << 32);
    }
    __syncthreads();
    const uint4* gm4 = reinterpret_cast<const uint4*>(g_M);

    for (unsigned g = 0; g < 16u; g++) {
        if (t == 0u) {
            while (ld_acquire(&g_gdone[g]) < 4u) __nanosleep(32);
            sh_nzg = g_rowNZ[g];
        }
        __syncthreads();
        if (t < 512u) {                                   // stage group g (8KB)
            unsigned x4 = g * 512u + t;
            uint4 v = gm4[x4];
            unsigned row = x4 >> 3, p = x4 & 7u;
            Ms[(size_t)row * 17u + 2u * p]      = ((unsigned long long)v.y << 32) | v.x;
            Ms[(size_t)row * 17u + 2u * p + 1u] = ((unsigned long long)v.w << 32) | v.z;
        }
        __syncthreads();

        if (t < 32u) {                                    // decision for block g
            unsigned long long vmb = vmArr[g], rvb = remv[g], nzb = sh_nzg;
            unsigned long long avail = vmb & ~rvb;
            unsigned long long keepmask = avail & ~nzb;
            unsigned long long serialm = avail & nzb;
            unsigned rowbase = g * 64u;
            if (serialm) {
                #pragma unroll
                for (int q = 0; q < 4; q++) {
                    if (!((serialm >> (q * 16)) & 0xFFFFull)) continue;
                    unsigned long long col[16];
                    #pragma unroll
                    for (int jj = 0; jj < 16; jj++)
                        col[jj] = Ms[(size_t)(rowbase + (unsigned)(q * 16 + jj)) * 17u + g];
                    #pragma unroll
                    for (int jj = 0; jj < 16; jj++) {
                        int j = q * 16 + jj;
                        if ((serialm >> j) & 1ull) {
                            unsigned long long below = (1ull << j) - 1ull;
                            if ((keepmask & col[jj] & below) == 0ull)
                                keepmask |= 1ull << j;
                        }
                    }
                }
            }
            if (t == 0u) keepw[g] = keepmask;
        }
        __syncthreads();
        {                                                 // OR kept rows into remv
            unsigned long long km = keepw[g];
            unsigned c = t >> 6, j = t & 63u;
            unsigned long long acc = ((km >> j) & 1ull)
                                   ? Ms[(size_t)(g * 64u + j) * 17u + c] : 0ull;
            #pragma unroll
            for (int off = 16; off; off >>= 1)
                acc |= __shfl_down_sync(0xFFFFFFFFu, acc, off);
            if ((t & 31u) == 0u) tmpOr[t >> 5] = acc;
        }
        __syncthreads();
        if (t < 16u) remv[t] |= tmpOr[2u * t] | tmpOr[2u * t + 1u];
        __syncthreads();
    }

    // ---- output ----
    {
        unsigned slot = t;
        int keep = (int)((keepw[slot >> 6] >> (slot & 63u)) & 1ull);
        float m = keep ? 1.0f : 0.0f;
        float4 b = g_boxes[slot];
        float4 inf = g_info[slot];
        float* o = out + (size_t)slot * 7;
        o[0] = __fmul_rn(b.x, m);  o[1] = __fmul_rn(b.y, m);
        o[2] = __fmul_rn(b.z, m);  o[3] = __fmul_rn(b.w, m);
        o[4] = __fmul_rn(inf.x, m); o[5] = __fmul_rn(inf.y, m);
        o[6] = __fmul_rn(inf.z, m);
        if (keepmode == 0)
            out[KTOP * 7 + slot] = m;
        else
            ((unsigned char*)(out + KTOP * 7))[slot] = (unsigned char)keep;
    }

    // ---- reset scratch for next graph replay ----
    if (t < 16u) { g_rowNZ[t] = 0ull; g_gdone[t] = 0u; }
    if (t == 0u) { g_sync1 = 0u; g_ticket = 0u; g_cntT = 0u; }
}

// ---------------- host ----------------
extern "C" void kernel_launch(void* const* d_in, const int* in_sizes, int n_in,
                              void* d_out, int out_size) {
    const float* pred = (const float*)d_in[0];
    float* out = (float*)d_out;
    int keepmode = 0;
    if (out_size == KTOP * 7 + KTOP / 4) keepmode = 1;

    k_score<<<NROWS / (TILES * TROWS), 256>>>(pred);          // 1 (streams + tail selection)
    size_t rest_smem = (size_t)KTOP * 17 * 8;                 // 139264B
    cudaFuncSetAttribute(k_rest, cudaFuncAttributeMaxDynamicSharedMemorySize,
                         (int)rest_smem);
    k_rest<<<GBLK, 1024, rest_smem>>>(pred, out, keepmode);   // 2
}

// round 14
// speedup vs baseline: 1.0882x; 1.0882x over previous
#include <cuda_runtime.h>
#include <cstdint>

#define NROWS  (1u << 20)
#define KTOP   1024
#define ECAP   8192
#define BIN0   0xBE80u
#define TOPBIN 0xBF7Fu
#define TILES  8
#define TROWS  32

// ---------------- scratch (module-load allocations, allowed) ----------------
__device__ unsigned            g_key[NROWS];
__device__ unsigned            g_cntT;
__device__ uint2               g_T[ECAP];
__device__ uint2               g_A[KTOP];
__device__ uint2               g_E2[ECAP];
__device__ float4              g_boxes[KTOP];
__device__ float4              g_info[KTOP];
__device__ unsigned            g_validw[32];
__device__ unsigned long long  g_rowNZ[16];
__device__ __align__(16) unsigned long long g_M[KTOP * 16];

// ---------------- K1: score kernel (lean, R12 version) ----------------------
__global__ void __launch_bounds__(256) k_score(const float* __restrict__ pred) {
    __shared__ float4 sbuf[2][TROWS * 85 / 4];
    unsigned t = threadIdx.x;
    size_t blockRow0 = (size_t)blockIdx.x * (TILES * TROWS);
    const float4* gsrc = reinterpret_cast<const float4*>(pred)
                         + blockRow0 * 85 / 4;

    {
        float4* dst = sbuf[0];
        #pragma unroll
        for (int k = 0; k < 3; k++) {
            unsigned i = t + (unsigned)k * 256u;
            if (i < 680u) {
                unsigned sa = (unsigned)__cvta_generic_to_shared(dst + i);
                asm volatile("cp.async.cg.shared.global [%0], [%1], 16;\n"
                             :: "r"(sa), "l"(gsrc + i));
            }
        }
        asm volatile("cp.async.commit_group;\n");
    }

    unsigned row = t >> 3, seg = t & 7u;
    #pragma unroll
    for (int tile = 0; tile < TILES; tile++) {
        if (tile + 1 < TILES) {
            float4* dst = sbuf[(tile + 1) & 1];
            const float4* src = gsrc + (size_t)(tile + 1) * 680u;
            #pragma unroll
            for (int k = 0; k < 3; k++) {
                unsigned i = t + (unsigned)k * 256u;
                if (i < 680u) {
                    unsigned sa = (unsigned)__cvta_generic_to_shared(dst + i);
                    asm volatile("cp.async.cg.shared.global [%0], [%1], 16;\n"
                                 :: "r"(sa), "l"(src + i));
                }
            }
            asm volatile("cp.async.commit_group;\n");
            asm volatile("cp.async.wait_group 1;\n");
        } else {
            asm volatile("cp.async.wait_group 0;\n");
        }
        __syncthreads();

        const float* s = reinterpret_cast<const float*>(sbuf[tile & 1]);
        const float* r = s + row * 85u;
        unsigned best = __float_as_uint(r[5 + seg * 10]);
        #pragma unroll
        for (int j = 1; j < 10; j++)
            best = max(best, __float_as_uint(r[5 + seg * 10 + j]));
        #pragma unroll
        for (int d = 4; d; d >>= 1)
            best = max(best, __shfl_down_sync(0xFFFFFFFFu, best, d, 8));
        if (seg == 0u) {
            float obj = r[4];
            float conf = __fmul_rn(obj, __uint_as_float(best));
            unsigned key = (conf >= 0.25f) ? (__float_as_uint(obj) | 0x80000000u)
                                           : 0x31914AD7u;
            unsigned grow = (unsigned)(blockRow0 + (size_t)tile * TROWS + row);
            g_key[grow] = key;
            if ((key >> 16) == TOPBIN) {
                unsigned pn = atomicAdd(&g_cntT, 1u);
                if (pn < ECAP) g_T[pn] = make_uint2(key, grow);
            }
        }
        __syncthreads();
    }
}

// ---- single-warp suffix-scan boundary finder over 256 smem bins ------------
__device__ __forceinline__ void sufscan_find(const unsigned* hist, unsigned K,
                                             unsigned* outBin, unsigned* outK) {
    unsigned t = threadIdx.x;
    if (t < 32u) {
        unsigned h[8], s[8], acc = 0u;
        #pragma unroll
        for (int i = 7; i >= 0; i--) { h[i] = hist[t * 8u + (unsigned)i]; acc += h[i]; s[i] = acc; }
        unsigned suf = acc;
        #pragma unroll
        for (int off = 1; off < 32; off <<= 1) {
            unsigned v = __shfl_down_sync(0xFFFFFFFFu, suf, off);
            if (t + (unsigned)off < 32u) suf += v;
        }
        unsigned base = suf - acc;
        #pragma unroll
        for (int i = 0; i < 8; i++) {
            unsigned Sinc = s[i] + base, Sexc = Sinc - h[i];
            if (Sexc < K && Sinc >= K) { *outBin = t * 8u + (unsigned)i; *outK = K - Sexc; }
        }
    }
}

// ---------------- K2: selection + sort + gather -----------------------------
__global__ void __launch_bounds__(1024) k_selg(const float* __restrict__ pred) {
    __shared__ unsigned long long pA[KTOP], pB[KTOP];
    __shared__ unsigned sidx[KTOP];
    __shared__ unsigned hist[256];
    __shared__ unsigned eq[128];
    __shared__ unsigned sh_bin, sh_K, sh_cntG, sh_cntEq, sh_cA, sh_cE;
    unsigned t = threadIdx.x;

    unsigned cntT = g_cntT;
    bool fb = !(cntT >= KTOP && cntT <= (unsigned)ECAP);
    const uint2* src;
    unsigned CE, K2, b1v, cntA;

    if (!fb) {
        src = g_T; CE = cntT; K2 = KTOP; b1v = TOPBIN; cntA = 0u;
    } else {
        if (t < 256u) hist[t] = 0u;
        if (t == 0u) { sh_cA = 0u; sh_cE = 0u; }
        __syncthreads();
        const uint4* kp = reinterpret_cast<const uint4*>(g_key);
        for (unsigned i = t; i < NROWS / 4; i += 1024u) {
            uint4 k4 = kp[i];
            unsigned b;
            b = (k4.x >> 16) - BIN0; if (b < 256u) atomicAdd(&hist[b], 1u);
            b = (k4.y >> 16) - BIN0; if (b < 256u) atomicAdd(&hist[b], 1u);
            b = (k4.z >> 16) - BIN0; if (b < 256u) atomicAdd(&hist[b], 1u);
            b = (k4.w >> 16) - BIN0; if (b < 256u) atomicAdd(&hist[b], 1u);
        }
        __syncthreads();
        sufscan_find(hist, KTOP, &sh_bin, &sh_K);
        __syncthreads();
        unsigned b1 = sh_bin + BIN0;
        unsigned Kb = sh_K;
        for (unsigned i = t; i < NROWS; i += 1024u) {
            unsigned key = g_key[i];
            unsigned bin = key >> 16;
            if (bin > b1 && bin <= TOPBIN) {
                unsigned pn = atomicAdd(&sh_cA, 1u);
                if (pn < KTOP) g_A[pn] = make_uint2(key, i);
            } else if (bin == b1) {
                unsigned pn = atomicAdd(&sh_cE, 1u);
                if (pn < ECAP) g_E2[pn] = make_uint2(key, i);
            }
        }
        __syncthreads();
        src = g_E2; CE = min(sh_cE, (unsigned)ECAP);
        K2 = Kb; b1v = b1; cntA = min(sh_cA, (unsigned)KTOP);
    }

    // pass A: hist of key bits[8:16)
    if (t < 256u) hist[t] = 0u;
    if (t == 0u) { sh_cntG = 0u; sh_cntEq = 0u; }
    __syncthreads();
    for (unsigned e = t; e < CE; e += 1024u)
        atomicAdd(&hist[(src[e].x >> 8) & 0xFFu], 1u);
    __syncthreads();
    sufscan_find(hist, K2, &sh_bin, &sh_K);
    __syncthreads();
    unsigned bh = sh_bin, K3 = sh_K;

    // pass B: hist of low 8 bits within sub-bin bh
    if (t < 256u) hist[t] = 0u;
    __syncthreads();
    for (unsigned e = t; e < CE; e += 1024u) {
        unsigned k = src[e].x;
        if (((k >> 8) & 0xFFu) == bh) atomicAdd(&hist[k & 0xFFu], 1u);
    }
    __syncthreads();
    sufscan_find(hist, K3, &sh_bin, &sh_K);
    __syncthreads();
    unsigned VkLow = (bh << 8) | sh_bin;
    unsigned teq = sh_K;
    unsigned Vk  = (b1v << 16) | VkLow;

    // classify
    if (t < cntA) {
        uint2 a = g_A[t];
        pA[t] = ((unsigned long long)a.x << 32) | (unsigned)(~a.y);
    }
    for (unsigned e = t; e < CE; e += 1024u) {
        uint2 v = src[e];
        unsigned low = v.x & 0xFFFFu;
        if (low > VkLow) {
            unsigned p = atomicAdd(&sh_cntG, 1u);
            pA[cntA + p] = ((unsigned long long)v.x << 32) | (unsigned)(~v.y);
        } else if (low == VkLow) {
            unsigned p = atomicAdd(&sh_cntEq, 1u);
            if (p < 128u) eq[p] = v.y;
        }
    }
    __syncthreads();
    unsigned cntG = sh_cntG, cntEq = min(sh_cntEq, 128u);

    // sort ties ascending by index
    if (cntEq <= 32u) {
        if (t < 32u) {
            unsigned val = (t < cntEq) ? eq[t] : 0xFFFFFFFFu;
            #pragma unroll
            for (unsigned kk = 2; kk <= 32; kk <<= 1)
                for (unsigned j = kk >> 1; j > 0; j >>= 1) {
                    unsigned other = __shfl_xor_sync(0xFFFFFFFFu, val, j);
                    bool up   = ((t & kk) == 0u);
                    bool lowp = ((t & j) == 0u);
                    unsigned mx = max(val, other), mn = min(val, other);
                    val = (lowp == up) ? mn : mx;
                }
            eq[t] = val;
        }
        __syncthreads();
    } else {
        if (t < 128u && t >= cntEq) eq[t] = 0xFFFFFFFFu;
        __syncthreads();
        for (unsigned kk = 2; kk <= 128; kk <<= 1)
            for (unsigned j = kk >> 1; j > 0; j >>= 1) {
                if (t < 128u) {
                    unsigned ixj = t ^ j;
                    if (ixj > t) {
                        unsigned a = eq[t], b = eq[ixj];
                        bool up = ((t & kk) == 0u);
                        if ((a > b) == up) { eq[t] = b; eq[ixj] = a; }
                    }
                }
                __syncthreads();
            }
    }
    if (t < teq)
        pA[cntA + cntG + t] = ((unsigned long long)Vk << 32) | (unsigned)(~eq[t]);
    __syncthreads();

    // hybrid bitonic 1024 descending by (key,~idx)
    unsigned long long val = pA[t];
    int cur = 1;
    for (unsigned kk = 2; kk <= KTOP; kk <<= 1) {
        for (unsigned j = kk >> 1; j > 0; j >>= 1) {
            bool up   = ((t & kk) == 0u);
            bool lowp = ((t & j) == 0u);
            unsigned long long other;
            if (j >= 32u) {
                unsigned long long* w = cur ? pB : pA;
                w[t] = val;
                __syncthreads();
                other = w[t ^ j];
                cur ^= 1;
            } else {
                other = __shfl_xor_sync(0xFFFFFFFFu, val, j);
            }
            unsigned long long mx = (val > other) ? val : other;
            unsigned long long mn = (val > other) ? other : val;
            val = (lowp == up) ? mx : mn;
        }
    }

    {
        unsigned key = (unsigned)(val >> 32);
        unsigned idx = ~(unsigned)val;
        sidx[t] = idx;
        int valid = (key >= (BIN0 << 16)) ? 1 : 0;
        unsigned bal = __ballot_sync(0xFFFFFFFFu, valid);
        if ((t & 31u) == 0u) g_validw[t >> 5] = bal;
    }
    __syncthreads();

    // gather: 8 threads per row, 8 passes of 128 slots
    {
        unsigned seg = t & 7u;
        #pragma unroll
        for (int pass = 0; pass < 8; pass++) {
            unsigned slot = (unsigned)pass * 128u + (t >> 3);
            unsigned idx = sidx[slot];
            const float* r = pred + (size_t)idx * 85u;
            unsigned best = __float_as_uint(__ldg(r + 5 + seg * 10));
            unsigned bi   = seg * 10u;
            #pragma unroll
            for (int j = 1; j < 10; j++) {
                unsigned v = __float_as_uint(__ldg(r + 5 + seg * 10 + j));
                if (v > best) { best = v; bi = seg * 10u + (unsigned)j; }
            }
            #pragma unroll
            for (int d = 4; d; d >>= 1) {
                unsigned ob = __shfl_down_sync(0xFFFFFFFFu, best, d, 8);
                unsigned oi = __shfl_down_sync(0xFFFFFFFFu, bi, d, 8);
                if (ob > best || (ob == best && oi < bi)) { best = ob; bi = oi; }
            }
            if (seg == 0u) {
                float cx = __ldg(r), cy = __ldg(r + 1), w = __ldg(r + 2),
                      h = __ldg(r + 3), obj = __ldg(r + 4);
                float c = __uint_as_float(best);
                float hw = __fmul_rn(w, 0.5f), hh = __fmul_rn(h, 0.5f);
                g_boxes[slot] = make_float4(__fsub_rn(cx, hw), __fsub_rn(cy, hh),
                                            __fadd_rn(cx, hw), __fadd_rn(cy, hh));
                g_info[slot]  = make_float4(obj, c, (float)bi, 0.0f);
            }
        }
    }
    if (t == 0u) g_cntT = 0u;                 // reset for next replay
}

// ---------------- K3: IoU bitmask (64 blocks, no syncs/spins) ---------------
__global__ void __launch_bounds__(256) k_iou() {
    __shared__ float4 sb[KTOP];
    unsigned t = threadIdx.x;
    for (unsigned x = t; x < KTOP; x += 256u) sb[x] = g_boxes[x];
    __syncthreads();
    unsigned w = blockIdx.x * 256u + t;
    unsigned i = w >> 4, blk = w & 15u;
    float4 bi = sb[i];
    float ai = __fmul_rn(__fsub_rn(bi.z, bi.x), __fsub_rn(bi.w, bi.y));
    unsigned long long bits = 0ull;
    unsigned jbase = blk * 64u;
    #pragma unroll 4
    for (int jj = 0; jj < 64; jj++) {
        float4 bj = sb[jbase + jj];
        float aj = __fmul_rn(__fsub_rn(bj.z, bj.x), __fsub_rn(bj.w, bj.y));
        float ltx = fmaxf(bi.x, bj.x), lty = fmaxf(bi.y, bj.y);
        float rbx = fminf(bi.z, bj.z), rby = fminf(bi.w, bj.w);
        float wx = fmaxf(__fsub_rn(rbx, ltx), 0.0f);
        float wy = fmaxf(__fsub_rn(rby, lty), 0.0f);
        float inter = __fmul_rn(wx, wy);
        float uni = __fsub_rn(__fadd_rn(ai, aj), inter);
        float iou = __fdiv_rn(inter, fmaxf(uni, 1e-9f));
        bits |= ((unsigned long long)(iou > 0.65f)) << jj;
    }
    g_M[(size_t)i * 16 + blk] = bits;

    unsigned long long selfm = (blk == (i >> 6)) ? (1ull << (i & 63u)) : 0ull;
    int nz = ((bits & ~selfm) != 0ull);
    unsigned bal = __ballot_sync(0xFFFFFFFFu, nz);
    unsigned lane = t & 31u;
    if (lane == 0u && (bal & 0xFFFFu))
        atomicOr(&g_rowNZ[i >> 6], 1ull << (i & 63u));
    if (lane == 16u && (bal >> 16))
        atomicOr(&g_rowNZ[i >> 6], 1ull << (i & 63u));
}

// ---------------- K4 (ncu slot #4): greedy NMS + output ---------------------
__global__ void __launch_bounds__(1024) k_nms(float* __restrict__ out,
                                              int keepmode) {
    extern __shared__ __align__(16) unsigned long long Ms[];   // 1024*17 u64
    __shared__ unsigned long long keepw[16], remv[16], vmArr[16], rowNZsh[16];
    __shared__ unsigned long long tmpOr[32];
    unsigned t = threadIdx.x;

    {   // stage 128KB matrix into stride-17 smem (1024 threads, 8 uint4 each)
        const uint4* gm4 = reinterpret_cast<const uint4*>(g_M);
        #pragma unroll
        for (unsigned x4 = t; x4 < 8192u; x4 += 1024u) {
            uint4 v = gm4[x4];
            unsigned row = x4 >> 3, p = x4 & 7u;
            Ms[(size_t)row * 17u + 2u * p]      = ((unsigned long long)v.y << 32) | v.x;
            Ms[(size_t)row * 17u + 2u * p + 1u] = ((unsigned long long)v.w << 32) | v.z;
        }
    }
    if (t < 16u) {
        remv[t]    = 0ull;
        rowNZsh[t] = g_rowNZ[t];
        vmArr[t]   = (unsigned long long)g_validw[2u * t]
                   | ((unsigned long long)g_validw[2u * t + 1u] << 32);
    }
    __syncthreads();

    for (unsigned g = 0; g < 16u; g++) {
        if (t < 32u) {
            unsigned long long vmb = vmArr[g], rvb = remv[g], nzb = rowNZsh[g];
            unsigned long long avail = vmb & ~rvb;
            unsigned long long keepmask = avail & ~nzb;
            unsigned long long serialm = avail & nzb;
            unsigned rowbase = g * 64u;
            if (serialm) {
                #pragma unroll
                for (int q = 0; q < 4; q++) {
                    if (!((serialm >> (q * 16)) & 0xFFFFull)) continue;
                    unsigned long long col[16];
                    #pragma unroll
                    for (int jj = 0; jj < 16; jj++)
                        col[jj] = Ms[(size_t)(rowbase + (unsigned)(q * 16 + jj)) * 17u + g];
                    #pragma unroll
                    for (int jj = 0; jj < 16; jj++) {
                        int j = q * 16 + jj;
                        if ((serialm >> j) & 1ull) {
                            unsigned long long below = (1ull << j) - 1ull;
                            if ((keepmask & col[jj] & below) == 0ull)
                                keepmask |= 1ull << j;
                        }
                    }
                }
            }
            if (t == 0u) keepw[g] = keepmask;
        }
        __syncthreads();
        {   // cross-group suppression OR (atomic-free reduce)
            unsigned long long km = keepw[g];
            unsigned c = t >> 6, j = t & 63u;
            unsigned long long acc = ((km >> j) & 1ull)
                                   ? Ms[(size_t)(g * 64u + j) * 17u + c] : 0ull;
            #pragma unroll
            for (int off = 16; off; off >>= 1)
                acc |= __shfl_down_sync(0xFFFFFFFFu, acc, off);
            if ((t & 31u) == 0u) tmpOr[t >> 5] = acc;
        }
        __syncthreads();
        if (t < 16u) remv[t] |= tmpOr[2u * t] | tmpOr[2u * t + 1u];
        __syncthreads();
    }

    // output
    {
        unsigned slot = t;
        int keep = (int)((keepw[slot >> 6] >> (slot & 63u)) & 1ull);
        float m = keep ? 1.0f : 0.0f;
        float4 b = g_boxes[slot];
        float4 inf = g_info[slot];
        float* o = out + (size_t)slot * 7;
        o[0] = __fmul_rn(b.x, m);  o[1] = __fmul_rn(b.y, m);
        o[2] = __fmul_rn(b.z, m);  o[3] = __fmul_rn(b.w, m);
        o[4] = __fmul_rn(inf.x, m); o[5] = __fmul_rn(inf.y, m);
        o[6] = __fmul_rn(inf.z, m);
        if (keepmode == 0)
            out[KTOP * 7 + slot] = m;
        else
            ((unsigned char*)(out + KTOP * 7))[slot] = (unsigned char)keep;
    }

    if (t < 16u) g_rowNZ[t] = 0ull;           // reset for next replay
}

// ---------------- host ----------------
extern "C" void kernel_launch(void* const* d_in, const int* in_sizes, int n_in,
                              void* d_out, int out_size) {
    const float* pred = (const float*)d_in[0];
    float* out = (float*)d_out;
    int keepmode = 0;
    if (out_size == KTOP * 7 + KTOP / 4) keepmode = 1;

    k_score<<<NROWS / (TILES * TROWS), 256>>>(pred);      // 1
    k_selg<<<1, 1024>>>(pred);                            // 2
    k_iou<<<64, 256>>>();                                 // 3
    size_t nms_smem = (size_t)KTOP * 17 * 8;              // 139264B
    cudaFuncSetAttribute(k_nms, cudaFuncAttributeMaxDynamicSharedMemorySize,
                         (int)nms_smem);
    k_nms<<<1, 1024, nms_smem>>>(out, keepmode);          // 4 <- ncu capture slot
}

// round 15
// speedup vs baseline: 1.1483x; 1.0553x over previous
#include <cuda_runtime.h>
#include <cstdint>

#define NROWS  (1u << 20)
#define KTOP   1024
#define ECAP   8192
#define BIN0   0xBE80u
#define TOPBIN 0xBF7Fu
#define TILES  8
#define TROWS  32

// ---------------- scratch (module-load allocations, allowed) ----------------
__device__ unsigned            g_key[NROWS];
__device__ unsigned            g_cntT;
__device__ uint2               g_T[ECAP];
__device__ uint2               g_A[KTOP];
__device__ uint2               g_E2[ECAP];
__device__ unsigned            g_order[KTOP];
__device__ float4              g_boxes[KTOP];
__device__ float4              g_info[KTOP];
__device__ unsigned            g_validw[32];
__device__ unsigned long long  g_rowNZ[16];
__device__ __align__(16) unsigned long long g_M[KTOP * 16];

// ---------------- K1: score kernel ----------------
__global__ void __launch_bounds__(256) k_score(const float* __restrict__ pred) {
    __shared__ float4 sbuf[2][TROWS * 85 / 4];
    unsigned t = threadIdx.x;
    size_t blockRow0 = (size_t)blockIdx.x * (TILES * TROWS);
    const float4* gsrc = reinterpret_cast<const float4*>(pred)
                         + blockRow0 * 85 / 4;

    {
        float4* dst = sbuf[0];
        #pragma unroll
        for (int k = 0; k < 3; k++) {
            unsigned i = t + (unsigned)k * 256u;
            if (i < 680u) {
                unsigned sa = (unsigned)__cvta_generic_to_shared(dst + i);
                asm volatile("cp.async.cg.shared.global [%0], [%1], 16;\n"
                             :: "r"(sa), "l"(gsrc + i));
            }
        }
        asm volatile("cp.async.commit_group;\n");
    }

    unsigned row = t >> 3, seg = t & 7u;
    #pragma unroll
    for (int tile = 0; tile < TILES; tile++) {
        if (tile + 1 < TILES) {
            float4* dst = sbuf[(tile + 1) & 1];
            const float4* src = gsrc + (size_t)(tile + 1) * 680u;
            #pragma unroll
            for (int k = 0; k < 3; k++) {
                unsigned i = t + (unsigned)k * 256u;
                if (i < 680u) {
                    unsigned sa = (unsigned)__cvta_generic_to_shared(dst + i);
                    asm volatile("cp.async.cg.shared.global [%0], [%1], 16;\n"
                                 :: "r"(sa), "l"(src + i));
                }
            }
            asm volatile("cp.async.commit_group;\n");
            asm volatile("cp.async.wait_group 1;\n");
        } else {
            asm volatile("cp.async.wait_group 0;\n");
        }
        __syncthreads();

        const float* s = reinterpret_cast<const float*>(sbuf[tile & 1]);
        const float* r = s + row * 85u;
        unsigned best = __float_as_uint(r[5 + seg * 10]);
        #pragma unroll
        for (int j = 1; j < 10; j++)
            best = max(best, __float_as_uint(r[5 + seg * 10 + j]));
        #pragma unroll
        for (int d = 4; d; d >>= 1)
            best = max(best, __shfl_down_sync(0xFFFFFFFFu, best, d, 8));
        if (seg == 0u) {
            float obj = r[4];
            float conf = __fmul_rn(obj, __uint_as_float(best));
            unsigned key = (conf >= 0.25f) ? (__float_as_uint(obj) | 0x80000000u)
                                           : 0x31914AD7u;
            unsigned grow = (unsigned)(blockRow0 + (size_t)tile * TROWS + row);
            g_key[grow] = key;
            if ((key >> 16) == TOPBIN) {
                unsigned pn = atomicAdd(&g_cntT, 1u);
                if (pn < ECAP) g_T[pn] = make_uint2(key, grow);
            }
        }
        __syncthreads();
    }
}

// ---- single-warp suffix-scan boundary finder over 256 smem bins ------------
__device__ __forceinline__ void sufscan_find(const unsigned* hist, unsigned K,
                                             unsigned* outBin, unsigned* outK) {
    unsigned t = threadIdx.x;
    if (t < 32u) {
        unsigned h[8], s[8], acc = 0u;
        #pragma unroll
        for (int i = 7; i >= 0; i--) { h[i] = hist[t * 8u + (unsigned)i]; acc += h[i]; s[i] = acc; }
        unsigned suf = acc;
        #pragma unroll
        for (int off = 1; off < 32; off <<= 1) {
            unsigned v = __shfl_down_sync(0xFFFFFFFFu, suf, off);
            if (t + (unsigned)off < 32u) suf += v;
        }
        unsigned base = suf - acc;
        #pragma unroll
        for (int i = 0; i < 8; i++) {
            unsigned Sinc = s[i] + base, Sexc = Sinc - h[i];
            if (Sexc < K && Sinc >= K) { *outBin = t * 8u + (unsigned)i; *outK = K - Sexc; }
        }
    }
}

// ---------------- K2: selection + sort --------------------------------------
__global__ void __launch_bounds__(1024) k_sel() {
    __shared__ unsigned long long pA[KTOP], pB[KTOP];
    __shared__ unsigned hist[256];
    __shared__ unsigned eq[128];
    __shared__ unsigned sh_bin, sh_K, sh_cntG, sh_cntEq, sh_cA, sh_cE;
    unsigned t = threadIdx.x;

    unsigned cntT = g_cntT;
    bool fb = !(cntT >= KTOP && cntT <= (unsigned)ECAP);
    const uint2* src;
    unsigned CE, K2, b1v, cntA;

    if (!fb) {
        src = g_T; CE = cntT; K2 = KTOP; b1v = TOPBIN; cntA = 0u;
    } else {
        if (t < 256u) hist[t] = 0u;
        if (t == 0u) { sh_cA = 0u; sh_cE = 0u; }
        __syncthreads();
        const uint4* kp = reinterpret_cast<const uint4*>(g_key);
        for (unsigned i = t; i < NROWS / 4; i += 1024u) {
            uint4 k4 = kp[i];
            unsigned b;
            b = (k4.x >> 16) - BIN0; if (b < 256u) atomicAdd(&hist[b], 1u);
            b = (k4.y >> 16) - BIN0; if (b < 256u) atomicAdd(&hist[b], 1u);
            b = (k4.z >> 16) - BIN0; if (b < 256u) atomicAdd(&hist[b], 1u);
            b = (k4.w >> 16) - BIN0; if (b < 256u) atomicAdd(&hist[b], 1u);
        }
        __syncthreads();
        sufscan_find(hist, KTOP, &sh_bin, &sh_K);
        __syncthreads();
        unsigned b1 = sh_bin + BIN0;
        unsigned Kb = sh_K;
        for (unsigned i = t; i < NROWS; i += 1024u) {
            unsigned key = g_key[i];
            unsigned bin = key >> 16;
            if (bin > b1 && bin <= TOPBIN) {
                unsigned pn = atomicAdd(&sh_cA, 1u);
                if (pn < KTOP) g_A[pn] = make_uint2(key, i);
            } else if (bin == b1) {
                unsigned pn = atomicAdd(&sh_cE, 1u);
                if (pn < ECAP) g_E2[pn] = make_uint2(key, i);
            }
        }
        __syncthreads();
        src = g_E2; CE = min(sh_cE, (unsigned)ECAP);
        K2 = Kb; b1v = b1; cntA = min(sh_cA, (unsigned)KTOP);
    }

    // pass A: hist of key bits[8:16)
    if (t < 256u) hist[t] = 0u;
    if (t == 0u) { sh_cntG = 0u; sh_cntEq = 0u; }
    __syncthreads();
    for (unsigned e = t; e < CE; e += 1024u)
        atomicAdd(&hist[(src[e].x >> 8) & 0xFFu], 1u);
    __syncthreads();
    sufscan_find(hist, K2, &sh_bin, &sh_K);
    __syncthreads();
    unsigned bh = sh_bin, K3 = sh_K;

    // pass B: hist of low 8 bits within sub-bin bh
    if (t < 256u) hist[t] = 0u;
    __syncthreads();
    for (unsigned e = t; e < CE; e += 1024u) {
        unsigned k = src[e].x;
        if (((k >> 8) & 0xFFu) == bh) atomicAdd(&hist[k & 0xFFu], 1u);
    }
    __syncthreads();
    sufscan_find(hist, K3, &sh_bin, &sh_K);
    __syncthreads();
    unsigned VkLow = (bh << 8) | sh_bin;
    unsigned teq = sh_K;
    unsigned Vk  = (b1v << 16) | VkLow;

    // classify
    if (t < cntA) {
        uint2 a = g_A[t];
        pA[t] = ((unsigned long long)a.x << 32) | (unsigned)(~a.y);
    }
    for (unsigned e = t; e < CE; e += 1024u) {
        uint2 v = src[e];
        unsigned low = v.x & 0xFFFFu;
        if (low > VkLow) {
            unsigned p = atomicAdd(&sh_cntG, 1u);
            pA[cntA + p] = ((unsigned long long)v.x << 32) | (unsigned)(~v.y);
        } else if (low == VkLow) {
            unsigned p = atomicAdd(&sh_cntEq, 1u);
            if (p < 128u) eq[p] = v.y;
        }
    }
    __syncthreads();
    unsigned cntG = sh_cntG, cntEq = min(sh_cntEq, 128u);

    // sort ties ascending by index
    if (cntEq <= 32u) {
        if (t < 32u) {
            unsigned val = (t < cntEq) ? eq[t] : 0xFFFFFFFFu;
            #pragma unroll
            for (unsigned kk = 2; kk <= 32; kk <<= 1)
                for (unsigned j = kk >> 1; j > 0; j >>= 1) {
                    unsigned other = __shfl_xor_sync(0xFFFFFFFFu, val, j);
                    bool up   = ((t & kk) == 0u);
                    bool lowp = ((t & j) == 0u);
                    unsigned mx = max(val, other), mn = min(val, other);
                    val = (lowp == up) ? mn : mx;
                }
            eq[t] = val;
        }
        __syncthreads();
    } else {
        if (t < 128u && t >= cntEq) eq[t] = 0xFFFFFFFFu;
        __syncthreads();
        for (unsigned kk = 2; kk <= 128; kk <<= 1)
            for (unsigned j = kk >> 1; j > 0; j >>= 1) {
                if (t < 128u) {
                    unsigned ixj = t ^ j;
                    if (ixj > t) {
                        unsigned a = eq[t], b = eq[ixj];
                        bool up = ((t & kk) == 0u);
                        if ((a > b) == up) { eq[t] = b; eq[ixj] = a; }
                    }
                }
                __syncthreads();
            }
    }
    if (t < teq)
        pA[cntA + cntG + t] = ((unsigned long long)Vk << 32) | (unsigned)(~eq[t]);
    __syncthreads();

    // hybrid bitonic 1024 descending by (key,~idx)
    unsigned long long val = pA[t];
    int cur = 1;
    for (unsigned kk = 2; kk <= KTOP; kk <<= 1) {
        for (unsigned j = kk >> 1; j > 0; j >>= 1) {
            bool up   = ((t & kk) == 0u);
            bool lowp = ((t & j) == 0u);
            unsigned long long other;
            if (j >= 32u) {
                unsigned long long* w = cur ? pB : pA;
                w[t] = val;
                __syncthreads();
                other = w[t ^ j];
                cur ^= 1;
            } else {
                other = __shfl_xor_sync(0xFFFFFFFFu, val, j);
            }
            unsigned long long mx = (val > other) ? val : other;
            unsigned long long mn = (val > other) ? other : val;
            val = (lowp == up) ? mx : mn;
        }
    }

    {
        unsigned key = (unsigned)(val >> 32);
        unsigned idx = ~(unsigned)val;
        g_order[t] = idx;
        int valid = (key >= (BIN0 << 16)) ? 1 : 0;
        unsigned bal = __ballot_sync(0xFFFFFFFFu, valid);
        if ((t & 31u) == 0u) g_validw[t >> 5] = bal;
    }
    if (t == 0u) g_cntT = 0u;
}

// ---------------- K3: gather winners (32 blocks) ----------------------------
__global__ void __launch_bounds__(256) k_gather(const float* __restrict__ pred) {
    unsigned t = threadIdx.x;
    unsigned slot = blockIdx.x * 32u + (t >> 3);
    unsigned seg = t & 7u;
    unsigned idx = g_order[slot];
    const float* r = pred + (size_t)idx * 85u;

    unsigned best = __float_as_uint(__ldg(r + 5 + seg * 10));
    unsigned bi   = seg * 10u;
    #pragma unroll
    for (int j = 1; j < 10; j++) {
        unsigned v = __float_as_uint(__ldg(r + 5 + seg * 10 + j));
        if (v > best) { best = v; bi = seg * 10u + (unsigned)j; }
    }
    #pragma unroll
    for (int d = 4; d; d >>= 1) {
        unsigned ob = __shfl_down_sync(0xFFFFFFFFu, best, d, 8);
        unsigned oi = __shfl_down_sync(0xFFFFFFFFu, bi, d, 8);
        if (ob > best || (ob == best && oi < bi)) { best = ob; bi = oi; }
    }
    if (seg == 0u) {
        float cx = __ldg(r), cy = __ldg(r + 1), w = __ldg(r + 2),
              h = __ldg(r + 3), obj = __ldg(r + 4);
        float c = __uint_as_float(best);
        float hw = __fmul_rn(w, 0.5f), hh = __fmul_rn(h, 0.5f);
        g_boxes[slot] = make_float4(__fsub_rn(cx, hw), __fsub_rn(cy, hh),
                                    __fadd_rn(cx, hw), __fadd_rn(cy, hh));
        g_info[slot]  = make_float4(obj, c, (float)bi, 0.0f);
    }
}

// ---------------- K4 (ncu slot #4): IoU bitmask (64 blocks) -----------------
__global__ void __launch_bounds__(256) k_iou() {
    __shared__ float4 sb[KTOP];
    unsigned t = threadIdx.x;
    for (unsigned x = t; x < KTOP; x += 256u) sb[x] = g_boxes[x];
    __syncthreads();
    unsigned w = blockIdx.x * 256u + t;
    unsigned i = w >> 4, blk = w & 15u;
    float4 bi = sb[i];
    float ai = __fmul_rn(__fsub_rn(bi.z, bi.x), __fsub_rn(bi.w, bi.y));
    unsigned long long bits = 0ull;
    unsigned jbase = blk * 64u;
    #pragma unroll 4
    for (int jj = 0; jj < 64; jj++) {
        float4 bj = sb[jbase + jj];
        float aj = __fmul_rn(__fsub_rn(bj.z, bj.x), __fsub_rn(bj.w, bj.y));
        float ltx = fmaxf(bi.x, bj.x), lty = fmaxf(bi.y, bj.y);
        float rbx = fminf(bi.z, bj.z), rby = fminf(bi.w, bj.w);
        float wx = fmaxf(__fsub_rn(rbx, ltx), 0.0f);
        float wy = fmaxf(__fsub_rn(rby, lty), 0.0f);
        float inter = __fmul_rn(wx, wy);
        float uni = __fsub_rn(__fadd_rn(ai, aj), inter);
        float iou = __fdiv_rn(inter, fmaxf(uni, 1e-9f));
        bits |= ((unsigned long long)(iou > 0.65f)) << jj;
    }
    g_M[(size_t)i * 16 + blk] = bits;

    unsigned long long selfm = (blk == (i >> 6)) ? (1ull << (i & 63u)) : 0ull;
    int nz = ((bits & ~selfm) != 0ull);
    unsigned bal = __ballot_sync(0xFFFFFFFFu, nz);
    unsigned lane = t & 31u;
    if (lane == 0u && (bal & 0xFFFFu))
        atomicOr(&g_rowNZ[i >> 6], 1ull << (i & 63u));
    if (lane == 16u && (bal >> 16))
        atomicOr(&g_rowNZ[i >> 6], 1ull << (i & 63u));
}

// ---------------- K5: greedy NMS (TMA staging + parallel OR) + output -------
__global__ void __launch_bounds__(1024) k_nms(float* __restrict__ out,
                                              int keepmode) {
    extern __shared__ __align__(16) unsigned long long Ms[];   // 16384 u64 (stride 16)
    __shared__ unsigned long long mbar;
    __shared__ unsigned long long tmp[16 * 33];                // padded transpose buf
    __shared__ unsigned long long keepw[16], remv[16], vmArr[16], rowNZsh[16];
    unsigned t = threadIdx.x;

    unsigned mb   = (unsigned)__cvta_generic_to_shared(&mbar);
    unsigned sdst = (unsigned)__cvta_generic_to_shared(Ms);
    if (t == 0u) {
        asm volatile("mbarrier.init.shared::cta.b64 [%0], 1;" :: "r"(mb));
        asm volatile("fence.proxy.async.shared::cta;" ::: "memory");
    }
    __syncthreads();
    if (t == 0u) {
        asm volatile("mbarrier.arrive.expect_tx.shared::cta.b64 _, [%0], %1;"
                     :: "r"(mb), "r"(131072u) : "memory");
        asm volatile("cp.async.bulk.shared::cta.global.mbarrier::complete_tx::bytes "
                     "[%0], [%1], %2, [%3];"
                     :: "r"(sdst), "l"(g_M), "r"(131072u), "r"(mb) : "memory");
    }
    if (t < 16u) {
        remv[t]    = 0ull;
        rowNZsh[t] = g_rowNZ[t];
        vmArr[t]   = (unsigned long long)g_validw[2u * t]
                   | ((unsigned long long)g_validw[2u * t + 1u] << 32);
    }
    asm volatile(
        "{\n\t.reg .pred P;\n"
        "WL%=:\n\tmbarrier.try_wait.parity.shared::cta.b64 P, [%0], %1;\n"
        "\t@P bra WD%=;\n\tbra WL%=;\nWD%=:\n\t}"
        :: "r"(mb), "r"(0u) : "memory");
    __syncthreads();

    unsigned w = t >> 5, lane = t & 31u;
    unsigned c2 = lane & 15u, half = lane >> 4;

    for (unsigned g = 0; g < 16u; g++) {
        if (t < 32u) {                          // decision: warp 0, broadcast reads
            unsigned long long vmb = vmArr[g], rvb = remv[g], nzb = rowNZsh[g];
            unsigned long long avail = vmb & ~rvb;
            unsigned long long keepmask = avail & ~nzb;
            unsigned long long serialm = avail & nzb;
            unsigned rowbase = g * 64u;
            if (serialm) {
                #pragma unroll
                for (int q = 0; q < 4; q++) {
                    if (!((serialm >> (q * 16)) & 0xFFFFull)) continue;
                    unsigned long long col[16];
                    #pragma unroll
                    for (int jj = 0; jj < 16; jj++)
                        col[jj] = Ms[(size_t)(rowbase + (unsigned)(q * 16 + jj)) * 16u + g];
                    #pragma unroll
                    for (int jj = 0; jj < 16; jj++) {
                        int j = q * 16 + jj;
                        if ((serialm >> j) & 1ull) {
                            unsigned long long below = (1ull << j) - 1ull;
                            if ((keepmask & col[jj] & below) == 0ull)
                                keepmask |= 1ull << j;
                        }
                    }
                }
            }
            if (t == 0u) keepw[g] = keepmask;
        }
        __syncthreads();
        {   // parallel cross-group OR: warp w -> rows 2w,2w+1; lane -> (half,col)
            unsigned long long km = keepw[g];
            unsigned j = 2u * w + half;
            unsigned long long acc = ((km >> j) & 1ull)
                                   ? Ms[(size_t)(g * 64u + j) * 16u + c2] : 0ull;
            acc |= __shfl_xor_sync(0xFFFFFFFFu, acc, 16);
            if (half == 0u) tmp[c2 * 33u + w] = acc;
        }
        __syncthreads();
        if (t < 512u) {                          // 16 warps reduce 32 partials each
            unsigned cc = t >> 5, l = t & 31u;
            unsigned long long v = tmp[cc * 33u + l];
            #pragma unroll
            for (int off = 16; off; off >>= 1)
                v |= __shfl_xor_sync(0xFFFFFFFFu, v, off);
            if (l == 0u) remv[cc] |= v;
        }
        __syncthreads();
    }

    // output
    {
        unsigned slot = t;
        int keep = (int)((keepw[slot >> 6] >> (slot & 63u)) & 1ull);
        float m = keep ? 1.0f : 0.0f;
        float4 b = g_boxes[slot];
        float4 inf = g_info[slot];
        float* o = out + (size_t)slot * 7;
        o[0] = __fmul_rn(b.x, m);  o[1] = __fmul_rn(b.y, m);
        o[2] = __fmul_rn(b.z, m);  o[3] = __fmul_rn(b.w, m);
        o[4] = __fmul_rn(inf.x, m); o[5] = __fmul_rn(inf.y, m);
        o[6] = __fmul_rn(inf.z, m);
        if (keepmode == 0)
            out[KTOP * 7 + slot] = m;
        else
            ((unsigned char*)(out + KTOP * 7))[slot] = (unsigned char)keep;
    }

    if (t < 16u) g_rowNZ[t] = 0ull;
}

// ---------------- host ----------------
extern "C" void kernel_launch(void* const* d_in, const int* in_sizes, int n_in,
                              void* d_out, int out_size) {
    const float* pred = (const float*)d_in[0];
    float* out = (float*)d_out;
    int keepmode = 0;
    if (out_size == KTOP * 7 + KTOP / 4) keepmode = 1;

    k_score<<<NROWS / (TILES * TROWS), 256>>>(pred);      // 1
    k_sel<<<1, 1024>>>();                                 // 2
    k_gather<<<32, 256>>>(pred);                          // 3
    k_iou<<<64, 256>>>();                                 // 4 <- ncu capture slot
    cudaFuncSetAttribute(k_nms, cudaFuncAttributeMaxDynamicSharedMemorySize,
                         131072);
    k_nms<<<1, 1024, 131072>>>(out, keepmode);            // 5
}

// round 16
// speedup vs baseline: 1.2130x; 1.0563x over previous
#include <cuda_runtime.h>
#include <cstdint>

#define NROWS  (1u << 20)
#define KTOP   1024
#define ECAP   8192
#define BIN0   0xBE80u
#define TOPBIN 0xBF7Fu
#define TILES  8
#define TROWS  32

// ---------------- scratch (module-load allocations, allowed) ----------------
__device__ unsigned            g_key[NROWS];
__device__ unsigned            g_cntT;
__device__ uint2               g_T[ECAP];
__device__ uint2               g_A[KTOP];
__device__ uint2               g_E2[ECAP];
__device__ unsigned            g_order[KTOP];
__device__ float4              g_boxes[KTOP];
__device__ float4              g_info[KTOP];
__device__ unsigned            g_validw[32];
__device__ unsigned long long  g_rowNZ[16];
__device__ __align__(16) unsigned long long g_M[KTOP * 16];

// ---------------- K1: score kernel ----------------
__global__ void __launch_bounds__(256) k_score(const float* __restrict__ pred) {
    __shared__ float4 sbuf[2][TROWS * 85 / 4];
    unsigned t = threadIdx.x;
    size_t blockRow0 = (size_t)blockIdx.x * (TILES * TROWS);
    const float4* gsrc = reinterpret_cast<const float4*>(pred)
                         + blockRow0 * 85 / 4;

    {
        float4* dst = sbuf[0];
        #pragma unroll
        for (int k = 0; k < 3; k++) {
            unsigned i = t + (unsigned)k * 256u;
            if (i < 680u) {
                unsigned sa = (unsigned)__cvta_generic_to_shared(dst + i);
                asm volatile("cp.async.cg.shared.global [%0], [%1], 16;\n"
                             :: "r"(sa), "l"(gsrc + i));
            }
        }
        asm volatile("cp.async.commit_group;\n");
    }

    unsigned row = t >> 3, seg = t & 7u;
    #pragma unroll
    for (int tile = 0; tile < TILES; tile++) {
        if (tile + 1 < TILES) {
            float4* dst = sbuf[(tile + 1) & 1];
            const float4* src = gsrc + (size_t)(tile + 1) * 680u;
            #pragma unroll
            for (int k = 0; k < 3; k++) {
                unsigned i = t + (unsigned)k * 256u;
                if (i < 680u) {
                    unsigned sa = (unsigned)__cvta_generic_to_shared(dst + i);
                    asm volatile("cp.async.cg.shared.global [%0], [%1], 16;\n"
                                 :: "r"(sa), "l"(src + i));
                }
            }
            asm volatile("cp.async.commit_group;\n");
            asm volatile("cp.async.wait_group 1;\n");
        } else {
            asm volatile("cp.async.wait_group 0;\n");
        }
        __syncthreads();

        const float* s = reinterpret_cast<const float*>(sbuf[tile & 1]);
        const float* r = s + row * 85u;
        unsigned best = __float_as_uint(r[5 + seg * 10]);
        #pragma unroll
        for (int j = 1; j < 10; j++)
            best = max(best, __float_as_uint(r[5 + seg * 10 + j]));
        #pragma unroll
        for (int d = 4; d; d >>= 1)
            best = max(best, __shfl_down_sync(0xFFFFFFFFu, best, d, 8));
        if (seg == 0u) {
            float obj = r[4];
            float conf = __fmul_rn(obj, __uint_as_float(best));
            unsigned key = (conf >= 0.25f) ? (__float_as_uint(obj) | 0x80000000u)
                                           : 0x31914AD7u;
            unsigned grow = (unsigned)(blockRow0 + (size_t)tile * TROWS + row);
            g_key[grow] = key;
            if ((key >> 16) == TOPBIN) {
                unsigned pn = atomicAdd(&g_cntT, 1u);
                if (pn < ECAP) g_T[pn] = make_uint2(key, grow);
            }
        }
        __syncthreads();
    }
}

// ---- single-warp suffix-scan boundary finder over 256 smem bins ------------
__device__ __forceinline__ void sufscan_find(const unsigned* hist, unsigned K,
                                             unsigned* outBin, unsigned* outK) {
    unsigned t = threadIdx.x;
    if (t < 32u) {
        unsigned h[8], s[8], acc = 0u;
        #pragma unroll
        for (int i = 7; i >= 0; i--) { h[i] = hist[t * 8u + (unsigned)i]; acc += h[i]; s[i] = acc; }
        unsigned suf = acc;
        #pragma unroll
        for (int off = 1; off < 32; off <<= 1) {
            unsigned v = __shfl_down_sync(0xFFFFFFFFu, suf, off);
            if (t + (unsigned)off < 32u) suf += v;
        }
        unsigned base = suf - acc;
        #pragma unroll
        for (int i = 0; i < 8; i++) {
            unsigned Sinc = s[i] + base, Sexc = Sinc - h[i];
            if (Sexc < K && Sinc >= K) { *outBin = t * 8u + (unsigned)i; *outK = K - Sexc; }
        }
    }
}

// ---------------- K2: selection + sort --------------------------------------
__global__ void __launch_bounds__(1024) k_sel() {
    __shared__ unsigned long long pA[KTOP], pB[KTOP];
    __shared__ unsigned hist[256];
    __shared__ unsigned eq[128];
    __shared__ unsigned sh_bin, sh_K, sh_cntG, sh_cntEq, sh_cA, sh_cE;
    unsigned t = threadIdx.x;

    unsigned cntT = g_cntT;
    bool fb = !(cntT >= KTOP && cntT <= (unsigned)ECAP);
    const uint2* src;
    unsigned CE, K2, b1v, cntA;

    if (!fb) {
        src = g_T; CE = cntT; K2 = KTOP; b1v = TOPBIN; cntA = 0u;
    } else {
        if (t < 256u) hist[t] = 0u;
        if (t == 0u) { sh_cA = 0u; sh_cE = 0u; }
        __syncthreads();
        const uint4* kp = reinterpret_cast<const uint4*>(g_key);
        for (unsigned i = t; i < NROWS / 4; i += 1024u) {
            uint4 k4 = kp[i];
            unsigned b;
            b = (k4.x >> 16) - BIN0; if (b < 256u) atomicAdd(&hist[b], 1u);
            b = (k4.y >> 16) - BIN0; if (b < 256u) atomicAdd(&hist[b], 1u);
            b = (k4.z >> 16) - BIN0; if (b < 256u) atomicAdd(&hist[b], 1u);
            b = (k4.w >> 16) - BIN0; if (b < 256u) atomicAdd(&hist[b], 1u);
        }
        __syncthreads();
        sufscan_find(hist, KTOP, &sh_bin, &sh_K);
        __syncthreads();
        unsigned b1 = sh_bin + BIN0;
        unsigned Kb = sh_K;
        for (unsigned i = t; i < NROWS; i += 1024u) {
            unsigned key = g_key[i];
            unsigned bin = key >> 16;
            if (bin > b1 && bin <= TOPBIN) {
                unsigned pn = atomicAdd(&sh_cA, 1u);
                if (pn < KTOP) g_A[pn] = make_uint2(key, i);
            } else if (bin == b1) {
                unsigned pn = atomicAdd(&sh_cE, 1u);
                if (pn < ECAP) g_E2[pn] = make_uint2(key, i);
            }
        }
        __syncthreads();
        src = g_E2; CE = min(sh_cE, (unsigned)ECAP);
        K2 = Kb; b1v = b1; cntA = min(sh_cA, (unsigned)KTOP);
    }

    // pass A: hist of key bits[8:16)
    if (t < 256u) hist[t] = 0u;
    if (t == 0u) { sh_cntG = 0u; sh_cntEq = 0u; }
    __syncthreads();
    for (unsigned e = t; e < CE; e += 1024u)
        atomicAdd(&hist[(src[e].x >> 8) & 0xFFu], 1u);
    __syncthreads();
    sufscan_find(hist, K2, &sh_bin, &sh_K);
    __syncthreads();
    unsigned bh = sh_bin, K3 = sh_K;

    // pass B: hist of low 8 bits within sub-bin bh
    if (t < 256u) hist[t] = 0u;
    __syncthreads();
    for (unsigned e = t; e < CE; e += 1024u) {
        unsigned k = src[e].x;
        if (((k >> 8) & 0xFFu) == bh) atomicAdd(&hist[k & 0xFFu], 1u);
    }
    __syncthreads();
    sufscan_find(hist, K3, &sh_bin, &sh_K);
    __syncthreads();
    unsigned VkLow = (bh << 8) | sh_bin;
    unsigned teq = sh_K;
    unsigned Vk  = (b1v << 16) | VkLow;

    // classify
    if (t < cntA) {
        uint2 a = g_A[t];
        pA[t] = ((unsigned long long)a.x << 32) | (unsigned)(~a.y);
    }
    for (unsigned e = t; e < CE; e += 1024u) {
        uint2 v = src[e];
        unsigned low = v.x & 0xFFFFu;
        if (low > VkLow) {
            unsigned p = atomicAdd(&sh_cntG, 1u);
            pA[cntA + p] = ((unsigned long long)v.x << 32) | (unsigned)(~v.y);
        } else if (low == VkLow) {
            unsigned p = atomicAdd(&sh_cntEq, 1u);
            if (p < 128u) eq[p] = v.y;
        }
    }
    __syncthreads();
    unsigned cntG = sh_cntG, cntEq = min(sh_cntEq, 128u);

    // sort ties ascending by index
    if (cntEq <= 32u) {
        if (t < 32u) {
            unsigned val = (t < cntEq) ? eq[t] : 0xFFFFFFFFu;
            #pragma unroll
            for (unsigned kk = 2; kk <= 32; kk <<= 1)
                for (unsigned j = kk >> 1; j > 0; j >>= 1) {
                    unsigned other = __shfl_xor_sync(0xFFFFFFFFu, val, j);
                    bool up   = ((t & kk) == 0u);
                    bool lowp = ((t & j) == 0u);
                    unsigned mx = max(val, other), mn = min(val, other);
                    val = (lowp == up) ? mn : mx;
                }
            eq[t] = val;
        }
        __syncthreads();
    } else {
        if (t < 128u && t >= cntEq) eq[t] = 0xFFFFFFFFu;
        __syncthreads();
        for (unsigned kk = 2; kk <= 128; kk <<= 1)
            for (unsigned j = kk >> 1; j > 0; j >>= 1) {
                if (t < 128u) {
                    unsigned ixj = t ^ j;
                    if (ixj > t) {
                        unsigned a = eq[t], b = eq[ixj];
                        bool up = ((t & kk) == 0u);
                        if ((a > b) == up) { eq[t] = b; eq[ixj] = a; }
                    }
                }
                __syncthreads();
            }
    }
    if (t < teq)
        pA[cntA + cntG + t] = ((unsigned long long)Vk << 32) | (unsigned)(~eq[t]);
    __syncthreads();

    // hybrid bitonic 1024 descending by (key,~idx)
    unsigned long long val = pA[t];
    int cur = 1;
    for (unsigned kk = 2; kk <= KTOP; kk <<= 1) {
        for (unsigned j = kk >> 1; j > 0; j >>= 1) {
            bool up   = ((t & kk) == 0u);
            bool lowp = ((t & j) == 0u);
            unsigned long long other;
            if (j >= 32u) {
                unsigned long long* w = cur ? pB : pA;
                w[t] = val;
                __syncthreads();
                other = w[t ^ j];
                cur ^= 1;
            } else {
                other = __shfl_xor_sync(0xFFFFFFFFu, val, j);
            }
            unsigned long long mx = (val > other) ? val : other;
            unsigned long long mn = (val > other) ? other : val;
            val = (lowp == up) ? mx : mn;
        }
    }

    {
        unsigned key = (unsigned)(val >> 32);
        unsigned idx = ~(unsigned)val;
        g_order[t] = idx;
        int valid = (key >= (BIN0 << 16)) ? 1 : 0;
        unsigned bal = __ballot_sync(0xFFFFFFFFu, valid);
        if ((t & 31u) == 0u) g_validw[t >> 5] = bal;
    }
    if (t == 0u) g_cntT = 0u;
}

// ---------------- K3: gather winners (32 blocks) ----------------------------
__global__ void __launch_bounds__(256) k_gather(const float* __restrict__ pred) {
    unsigned t = threadIdx.x;
    unsigned slot = blockIdx.x * 32u + (t >> 3);
    unsigned seg = t & 7u;
    unsigned idx = g_order[slot];
    const float* r = pred + (size_t)idx * 85u;

    unsigned best = __float_as_uint(__ldg(r + 5 + seg * 10));
    unsigned bi   = seg * 10u;
    #pragma unroll
    for (int j = 1; j < 10; j++) {
        unsigned v = __float_as_uint(__ldg(r + 5 + seg * 10 + j));
        if (v > best) { best = v; bi = seg * 10u + (unsigned)j; }
    }
    #pragma unroll
    for (int d = 4; d; d >>= 1) {
        unsigned ob = __shfl_down_sync(0xFFFFFFFFu, best, d, 8);
        unsigned oi = __shfl_down_sync(0xFFFFFFFFu, bi, d, 8);
        if (ob > best || (ob == best && oi < bi)) { best = ob; bi = oi; }
    }
    if (seg == 0u) {
        float cx = __ldg(r), cy = __ldg(r + 1), w = __ldg(r + 2),
              h = __ldg(r + 3), obj = __ldg(r + 4);
        float c = __uint_as_float(best);
        float hw = __fmul_rn(w, 0.5f), hh = __fmul_rn(h, 0.5f);
        g_boxes[slot] = make_float4(__fsub_rn(cx, hw), __fsub_rn(cy, hh),
                                    __fadd_rn(cx, hw), __fadd_rn(cy, hh));
        g_info[slot]  = make_float4(obj, c, (float)bi, 0.0f);
    }
}

// ---------------- K4 (ncu slot #4): IoU, 64 blocks x 1024 threads -----------
// thread = (row, word, quarter): 16 exact divs each; quarters merged by shfl.
__global__ void __launch_bounds__(1024) k_iou() {
    __shared__ float4 sb[KTOP];
    unsigned t = threadIdx.x;
    sb[t] = g_boxes[t];
    __syncthreads();

    unsigned unit = blockIdx.x * 1024u + t;
    unsigned i   = unit >> 6;              // row 0..1023
    unsigned sub = unit & 63u;
    unsigned blk = sub >> 2;               // word 0..15
    unsigned q   = sub & 3u;               // quarter 0..3
    float4 bi = sb[i];
    float ai = __fmul_rn(__fsub_rn(bi.z, bi.x), __fsub_rn(bi.w, bi.y));
    unsigned long long bits = 0ull;
    unsigned jbase = blk * 64u + q * 16u;
    #pragma unroll
    for (int jj = 0; jj < 16; jj++) {
        float4 bj = sb[jbase + (unsigned)jj];
        float aj = __fmul_rn(__fsub_rn(bj.z, bj.x), __fsub_rn(bj.w, bj.y));
        float ltx = fmaxf(bi.x, bj.x), lty = fmaxf(bi.y, bj.y);
        float rbx = fminf(bi.z, bj.z), rby = fminf(bi.w, bj.w);
        float wx = fmaxf(__fsub_rn(rbx, ltx), 0.0f);
        float wy = fmaxf(__fsub_rn(rby, lty), 0.0f);
        float inter = __fmul_rn(wx, wy);
        float uni = __fsub_rn(__fadd_rn(ai, aj), inter);
        float iou = __fdiv_rn(inter, fmaxf(uni, 1e-9f));
        bits |= ((unsigned long long)(iou > 0.65f)) << (q * 16u + (unsigned)jj);
    }
    bits |= __shfl_xor_sync(0xFFFFFFFFu, bits, 1);
    bits |= __shfl_xor_sync(0xFFFFFFFFu, bits, 2);
    int nz = 0;
    if (q == 0u) {
        g_M[(size_t)i * 16 + blk] = bits;
        unsigned long long selfm = (blk == (i >> 6)) ? (1ull << (i & 63u)) : 0ull;
        nz = ((bits & ~selfm) != 0ull);
    }
    unsigned bal = __ballot_sync(0xFFFFFFFFu, nz);
    if ((t & 31u) == 0u && bal)
        atomicOr(&g_rowNZ[i >> 6], 1ull << (i & 63u));
}

// ---------------- K5: greedy NMS (TMA staging + parallel OR) + output -------
__global__ void __launch_bounds__(1024) k_nms(float* __restrict__ out,
                                              int keepmode) {
    extern __shared__ __align__(16) unsigned long long Ms[];   // 16384 u64 (stride 16)
    __shared__ unsigned long long mbar;
    __shared__ unsigned long long tmp[16 * 33];
    __shared__ unsigned long long keepw[16], remv[16], vmArr[16], rowNZsh[16];
    unsigned t = threadIdx.x;

    unsigned mb   = (unsigned)__cvta_generic_to_shared(&mbar);
    unsigned sdst = (unsigned)__cvta_generic_to_shared(Ms);
    if (t == 0u) {
        asm volatile("mbarrier.init.shared::cta.b64 [%0], 1;" :: "r"(mb));
        asm volatile("fence.proxy.async.shared::cta;" ::: "memory");
    }
    __syncthreads();
    if (t == 0u) {
        asm volatile("mbarrier.arrive.expect_tx.shared::cta.b64 _, [%0], %1;"
                     :: "r"(mb), "r"(131072u) : "memory");
        asm volatile("cp.async.bulk.shared::cta.global.mbarrier::complete_tx::bytes "
                     "[%0], [%1], %2, [%3];"
                     :: "r"(sdst), "l"(g_M), "r"(131072u), "r"(mb) : "memory");
    }
    if (t < 16u) {
        remv[t]    = 0ull;
        rowNZsh[t] = g_rowNZ[t];
        vmArr[t]   = (unsigned long long)g_validw[2u * t]
                   | ((unsigned long long)g_validw[2u * t + 1u] << 32);
    }
    asm volatile(
        "{\n\t.reg .pred P;\n"
        "WL%=:\n\tmbarrier.try_wait.parity.shared::cta.b64 P, [%0], %1;\n"
        "\t@P bra WD%=;\n\tbra WL%=;\nWD%=:\n\t}"
        :: "r"(mb), "r"(0u) : "memory");
    __syncthreads();

    unsigned w = t >> 5, lane = t & 31u;
    unsigned c2 = lane & 15u, half = lane >> 4;

    for (unsigned g = 0; g < 16u; g++) {
        if (t < 32u) {
            unsigned long long vmb = vmArr[g], rvb = remv[g], nzb = rowNZsh[g];
            unsigned long long avail = vmb & ~rvb;
            unsigned long long keepmask = avail & ~nzb;
            unsigned long long serialm = avail & nzb;
            unsigned rowbase = g * 64u;
            if (serialm) {
                #pragma unroll
                for (int q = 0; q < 4; q++) {
                    if (!((serialm >> (q * 16)) & 0xFFFFull)) continue;
                    unsigned long long col[16];
                    #pragma unroll
                    for (int jj = 0; jj < 16; jj++)
                        col[jj] = Ms[(size_t)(rowbase + (unsigned)(q * 16 + jj)) * 16u + g];
                    #pragma unroll
                    for (int jj = 0; jj < 16; jj++) {
                        int j = q * 16 + jj;
                        if ((serialm >> j) & 1ull) {
                            unsigned long long below = (1ull << j) - 1ull;
                            if ((keepmask & col[jj] & below) == 0ull)
                                keepmask |= 1ull << j;
                        }
                    }
                }
            }
            if (t == 0u) keepw[g] = keepmask;
        }
        __syncthreads();
        {   // parallel cross-group OR: warp w -> rows 2w,2w+1; lane -> (half,col)
            unsigned long long km = keepw[g];
            unsigned j = 2u * w + half;
            unsigned long long acc = ((km >> j) & 1ull)
                                   ? Ms[(size_t)(g * 64u + j) * 16u + c2] : 0ull;
            acc |= __shfl_xor_sync(0xFFFFFFFFu, acc, 16);
            if (half == 0u) tmp[c2 * 33u + w] = acc;
        }
        __syncthreads();
        if (t < 512u) {
            unsigned cc = t >> 5, l = t & 31u;
            unsigned long long v = tmp[cc * 33u + l];
            #pragma unroll
            for (int off = 16; off; off >>= 1)
                v |= __shfl_xor_sync(0xFFFFFFFFu, v, off);
            if (l == 0u) remv[cc] |= v;
        }
        __syncthreads();
    }

    // output
    {
        unsigned slot = t;
        int keep = (int)((keepw[slot >> 6] >> (slot & 63u)) & 1ull);
        float m = keep ? 1.0f : 0.0f;
        float4 b = g_boxes[slot];
        float4 inf = g_info[slot];
        float* o = out + (size_t)slot * 7;
        o[0] = __fmul_rn(b.x, m);  o[1] = __fmul_rn(b.y, m);
        o[2] = __fmul_rn(b.z, m);  o[3] = __fmul_rn(b.w, m);
        o[4] = __fmul_rn(inf.x, m); o[5] = __fmul_rn(inf.y, m);
        o[6] = __fmul_rn(inf.z, m);
        if (keepmode == 0)
            out[KTOP * 7 + slot] = m;
        else
            ((unsigned char*)(out + KTOP * 7))[slot] = (unsigned char)keep;
    }

    if (t < 16u) g_rowNZ[t] = 0ull;
}

// ---------------- host ----------------
extern "C" void kernel_launch(void* const* d_in, const int* in_sizes, int n_in,
                              void* d_out, int out_size) {
    const float* pred = (const float*)d_in[0];
    float* out = (float*)d_out;
    int keepmode = 0;
    if (out_size == KTOP * 7 + KTOP / 4) keepmode = 1;

    k_score<<<NROWS / (TILES * TROWS), 256>>>(pred);      // 1
    k_sel<<<1, 1024>>>();                                 // 2
    k_gather<<<32, 256>>>(pred);                          // 3
    k_iou<<<64, 1024>>>();                                // 4 <- ncu capture slot
    cudaFuncSetAttribute(k_nms, cudaFuncAttributeMaxDynamicSharedMemorySize,
                         131072);
    k_nms<<<1, 1024, 131072>>>(out, keepmode);            // 5
}

// round 17
// speedup vs baseline: 1.2193x; 1.0052x over previous
#include <cuda_runtime.h>
#include <cstdint>

#define NROWS  (1u << 20)
#define KTOP   1024
#define ECAP   8192
#define BIN0   0xBE80u
#define TOPBIN 0xBF7Fu
#define TILES  8
#define TROWS  32

// ---------------- scratch (module-load allocations, allowed) ----------------
__device__ unsigned            g_key[NROWS];
__device__ unsigned            g_cntT;
__device__ uint2               g_T[ECAP];
__device__ uint2               g_A[KTOP];
__device__ uint2               g_E2[ECAP];
__device__ unsigned            g_order[KTOP];
__device__ float4              g_boxes[KTOP];
__device__ float4              g_info[KTOP];
__device__ unsigned            g_validw[32];
__device__ unsigned long long  g_rowNZ[16];
__device__ __align__(16) unsigned long long g_M[KTOP * 16];

// ---------------- K1: score kernel ----------------
__global__ void __launch_bounds__(256) k_score(const float* __restrict__ pred) {
    __shared__ float4 sbuf[2][TROWS * 85 / 4];
    unsigned t = threadIdx.x;
    size_t blockRow0 = (size_t)blockIdx.x * (TILES * TROWS);
    const float4* gsrc = reinterpret_cast<const float4*>(pred)
                         + blockRow0 * 85 / 4;

    {
        float4* dst = sbuf[0];
        #pragma unroll
        for (int k = 0; k < 3; k++) {
            unsigned i = t + (unsigned)k * 256u;
            if (i < 680u) {
                unsigned sa = (unsigned)__cvta_generic_to_shared(dst + i);
                asm volatile("cp.async.cg.shared.global [%0], [%1], 16;\n"
                             :: "r"(sa), "l"(gsrc + i));
            }
        }
        asm volatile("cp.async.commit_group;\n");
    }

    unsigned row = t >> 3, seg = t & 7u;
    #pragma unroll
    for (int tile = 0; tile < TILES; tile++) {
        if (tile + 1 < TILES) {
            float4* dst = sbuf[(tile + 1) & 1];
            const float4* src = gsrc + (size_t)(tile + 1) * 680u;
            #pragma unroll
            for (int k = 0; k < 3; k++) {
                unsigned i = t + (unsigned)k * 256u;
                if (i < 680u) {
                    unsigned sa = (unsigned)__cvta_generic_to_shared(dst + i);
                    asm volatile("cp.async.cg.shared.global [%0], [%1], 16;\n"
                                 :: "r"(sa), "l"(src + i));
                }
            }
            asm volatile("cp.async.commit_group;\n");
            asm volatile("cp.async.wait_group 1;\n");
        } else {
            asm volatile("cp.async.wait_group 0;\n");
        }
        __syncthreads();

        const float* s = reinterpret_cast<const float*>(sbuf[tile & 1]);
        const float* r = s + row * 85u;
        unsigned best = __float_as_uint(r[5 + seg * 10]);
        #pragma unroll
        for (int j = 1; j < 10; j++)
            best = max(best, __float_as_uint(r[5 + seg * 10 + j]));
        #pragma unroll
        for (int d = 4; d; d >>= 1)
            best = max(best, __shfl_down_sync(0xFFFFFFFFu, best, d, 8));
        if (seg == 0u) {
            float obj = r[4];
            float conf = __fmul_rn(obj, __uint_as_float(best));
            unsigned key = (conf >= 0.25f) ? (__float_as_uint(obj) | 0x80000000u)
                                           : 0x31914AD7u;
            unsigned grow = (unsigned)(blockRow0 + (size_t)tile * TROWS + row);
            g_key[grow] = key;
            if ((key >> 16) == TOPBIN) {
                unsigned pn = atomicAdd(&g_cntT, 1u);
                if (pn < ECAP) g_T[pn] = make_uint2(key, grow);
            }
        }
        __syncthreads();
    }
}

// ---- single-warp suffix-scan boundary finder over 256 smem bins ------------
__device__ __forceinline__ void sufscan_find(const unsigned* hist, unsigned K,
                                             unsigned* outBin, unsigned* outK) {
    unsigned t = threadIdx.x;
    if (t < 32u) {
        unsigned h[8], s[8], acc = 0u;
        #pragma unroll
        for (int i = 7; i >= 0; i--) { h[i] = hist[t * 8u + (unsigned)i]; acc += h[i]; s[i] = acc; }
        unsigned suf = acc;
        #pragma unroll
        for (int off = 1; off < 32; off <<= 1) {
            unsigned v = __shfl_down_sync(0xFFFFFFFFu, suf, off);
            if (t + (unsigned)off < 32u) suf += v;
        }
        unsigned base = suf - acc;
        #pragma unroll
        for (int i = 0; i < 8; i++) {
            unsigned Sinc = s[i] + base, Sexc = Sinc - h[i];
            if (Sexc < K && Sinc >= K) { *outBin = t * 8u + (unsigned)i; *outK = K - Sexc; }
        }
    }
}

// ---------------- K2: selection + sort --------------------------------------
__global__ void __launch_bounds__(1024) k_sel() {
    __shared__ unsigned long long pA[KTOP], pB[KTOP];
    __shared__ unsigned hist[256];
    __shared__ unsigned eq[128];
    __shared__ unsigned sh_bin, sh_K, sh_cntG, sh_cntEq, sh_cA, sh_cE;
    unsigned t = threadIdx.x;

    unsigned cntT = g_cntT;
    bool fb = !(cntT >= KTOP && cntT <= (unsigned)ECAP);
    const uint2* src;
    unsigned CE, K2, b1v, cntA;

    if (!fb) {
        src = g_T; CE = cntT; K2 = KTOP; b1v = TOPBIN; cntA = 0u;
    } else {
        if (t < 256u) hist[t] = 0u;
        if (t == 0u) { sh_cA = 0u; sh_cE = 0u; }
        __syncthreads();
        const uint4* kp = reinterpret_cast<const uint4*>(g_key);
        for (unsigned i = t; i < NROWS / 4; i += 1024u) {
            uint4 k4 = kp[i];
            unsigned b;
            b = (k4.x >> 16) - BIN0; if (b < 256u) atomicAdd(&hist[b], 1u);
            b = (k4.y >> 16) - BIN0; if (b < 256u) atomicAdd(&hist[b], 1u);
            b = (k4.z >> 16) - BIN0; if (b < 256u) atomicAdd(&hist[b], 1u);
            b = (k4.w >> 16) - BIN0; if (b < 256u) atomicAdd(&hist[b], 1u);
        }
        __syncthreads();
        sufscan_find(hist, KTOP, &sh_bin, &sh_K);
        __syncthreads();
        unsigned b1 = sh_bin + BIN0;
        unsigned Kb = sh_K;
        for (unsigned i = t; i < NROWS; i += 1024u) {
            unsigned key = g_key[i];
            unsigned bin = key >> 16;
            if (bin > b1 && bin <= TOPBIN) {
                unsigned pn = atomicAdd(&sh_cA, 1u);
                if (pn < KTOP) g_A[pn] = make_uint2(key, i);
            } else if (bin == b1) {
                unsigned pn = atomicAdd(&sh_cE, 1u);
                if (pn < ECAP) g_E2[pn] = make_uint2(key, i);
            }
        }
        __syncthreads();
        src = g_E2; CE = min(sh_cE, (unsigned)ECAP);
        K2 = Kb; b1v = b1; cntA = min(sh_cA, (unsigned)KTOP);
    }

    // pass A: hist of key bits[8:16)
    if (t < 256u) hist[t] = 0u;
    if (t == 0u) { sh_cntG = 0u; sh_cntEq = 0u; }
    __syncthreads();
    for (unsigned e = t; e < CE; e += 1024u)
        atomicAdd(&hist[(src[e].x >> 8) & 0xFFu], 1u);
    __syncthreads();
    sufscan_find(hist, K2, &sh_bin, &sh_K);
    __syncthreads();
    unsigned bh = sh_bin, K3 = sh_K;

    // pass B: hist of low 8 bits within sub-bin bh
    if (t < 256u) hist[t] = 0u;
    __syncthreads();
    for (unsigned e = t; e < CE; e += 1024u) {
        unsigned k = src[e].x;
        if (((k >> 8) & 0xFFu) == bh) atomicAdd(&hist[k & 0xFFu], 1u);
    }
    __syncthreads();
    sufscan_find(hist, K3, &sh_bin, &sh_K);
    __syncthreads();
    unsigned VkLow = (bh << 8) | sh_bin;
    unsigned teq = sh_K;
    unsigned Vk  = (b1v << 16) | VkLow;

    // classify
    if (t < cntA) {
        uint2 a = g_A[t];
        pA[t] = ((unsigned long long)a.x << 32) | (unsigned)(~a.y);
    }
    for (unsigned e = t; e < CE; e += 1024u) {
        uint2 v = src[e];
        unsigned low = v.x & 0xFFFFu;
        if (low > VkLow) {
            unsigned p = atomicAdd(&sh_cntG, 1u);
            pA[cntA + p] = ((unsigned long long)v.x << 32) | (unsigned)(~v.y);
        } else if (low == VkLow) {
            unsigned p = atomicAdd(&sh_cntEq, 1u);
            if (p < 128u) eq[p] = v.y;
        }
    }
    __syncthreads();
    unsigned cntG = sh_cntG, cntEq = min(sh_cntEq, 128u);

    // sort ties ascending by index
    if (cntEq <= 32u) {
        if (t < 32u) {
            unsigned val = (t < cntEq) ? eq[t] : 0xFFFFFFFFu;
            #pragma unroll
            for (unsigned kk = 2; kk <= 32; kk <<= 1)
                for (unsigned j = kk >> 1; j > 0; j >>= 1) {
                    unsigned other = __shfl_xor_sync(0xFFFFFFFFu, val, j);
                    bool up   = ((t & kk) == 0u);
                    bool lowp = ((t & j) == 0u);
                    unsigned mx = max(val, other), mn = min(val, other);
                    val = (lowp == up) ? mn : mx;
                }
            eq[t] = val;
        }
        __syncthreads();
    } else {
        if (t < 128u && t >= cntEq) eq[t] = 0xFFFFFFFFu;
        __syncthreads();
        for (unsigned kk = 2; kk <= 128; kk <<= 1)
            for (unsigned j = kk >> 1; j > 0; j >>= 1) {
                if (t < 128u) {
                    unsigned ixj = t ^ j;
                    if (ixj > t) {
                        unsigned a = eq[t], b = eq[ixj];
                        bool up = ((t & kk) == 0u);
                        if ((a > b) == up) { eq[t] = b; eq[ixj] = a; }
                    }
                }
                __syncthreads();
            }
    }
    if (t < teq)
        pA[cntA + cntG + t] = ((unsigned long long)Vk << 32) | (unsigned)(~eq[t]);
    __syncthreads();

    // hybrid bitonic 1024 descending by (key,~idx)
    unsigned long long val = pA[t];
    int cur = 1;
    for (unsigned kk = 2; kk <= KTOP; kk <<= 1) {
        for (unsigned j = kk >> 1; j > 0; j >>= 1) {
            bool up   = ((t & kk) == 0u);
            bool lowp = ((t & j) == 0u);
            unsigned long long other;
            if (j >= 32u) {
                unsigned long long* w = cur ? pB : pA;
                w[t] = val;
                __syncthreads();
                other = w[t ^ j];
                cur ^= 1;
            } else {
                other = __shfl_xor_sync(0xFFFFFFFFu, val, j);
            }
            unsigned long long mx = (val > other) ? val : other;
            unsigned long long mn = (val > other) ? other : val;
            val = (lowp == up) ? mx : mn;
        }
    }

    {
        unsigned key = (unsigned)(val >> 32);
        unsigned idx = ~(unsigned)val;
        g_order[t] = idx;
        int valid = (key >= (BIN0 << 16)) ? 1 : 0;
        unsigned bal = __ballot_sync(0xFFFFFFFFu, valid);
        if ((t & 31u) == 0u) g_validw[t >> 5] = bal;
    }
    if (t == 0u) g_cntT = 0u;
}

// ---------------- K3: gather winners (32 blocks) ----------------------------
__global__ void __launch_bounds__(256) k_gather(const float* __restrict__ pred) {
    unsigned t = threadIdx.x;
    unsigned slot = blockIdx.x * 32u + (t >> 3);
    unsigned seg = t & 7u;
    unsigned idx = g_order[slot];
    const float* r = pred + (size_t)idx * 85u;

    unsigned best = __float_as_uint(__ldg(r + 5 + seg * 10));
    unsigned bi   = seg * 10u;
    #pragma unroll
    for (int j = 1; j < 10; j++) {
        unsigned v = __float_as_uint(__ldg(r + 5 + seg * 10 + j));
        if (v > best) { best = v; bi = seg * 10u + (unsigned)j; }
    }
    #pragma unroll
    for (int d = 4; d; d >>= 1) {
        unsigned ob = __shfl_down_sync(0xFFFFFFFFu, best, d, 8);
        unsigned oi = __shfl_down_sync(0xFFFFFFFFu, bi, d, 8);
        if (ob > best || (ob == best && oi < bi)) { best = ob; bi = oi; }
    }
    if (seg == 0u) {
        float cx = __ldg(r), cy = __ldg(r + 1), w = __ldg(r + 2),
              h = __ldg(r + 3), obj = __ldg(r + 4);
        float c = __uint_as_float(best);
        float hw = __fmul_rn(w, 0.5f), hh = __fmul_rn(h, 0.5f);
        g_boxes[slot] = make_float4(__fsub_rn(cx, hw), __fsub_rn(cy, hh),
                                    __fadd_rn(cx, hw), __fadd_rn(cy, hh));
        g_info[slot]  = make_float4(obj, c, (float)bi, 0.0f);
    }
}

// ---------------- K4 (ncu slot #4): IoU, conflict-free + ballot assembly ----
// thread s in [0,64) of row i handles columns j = s + 64*jj: lanes read 32
// CONSECUTIVE sb entries (no bank conflicts); words assembled via ballot.
__global__ void __launch_bounds__(1024) k_iou() {
    __shared__ float4 sb[KTOP];
    unsigned t = threadIdx.x;
    sb[t] = g_boxes[t];
    __syncthreads();

    unsigned unit = blockIdx.x * 1024u + t;
    unsigned i    = unit >> 6;             // row 0..1023
    unsigned s    = unit & 63u;            // bit position 0..63
    unsigned lane = t & 31u;
    unsigned half = (s >> 5) & 1u;         // 0: bits 0..31, 1: bits 32..63

    float4 bi = sb[i];
    float ai = __fmul_rn(__fsub_rn(bi.z, bi.x), __fsub_rn(bi.w, bi.y));

    unsigned* gm32 = reinterpret_cast<unsigned*>(g_M);
    unsigned nzacc = 0u;
    unsigned iw = i >> 6, ib = i & 63u;

    #pragma unroll
    for (unsigned jj = 0; jj < 16u; jj++) {
        unsigned j = s + (jj << 6);
        float4 bj = sb[j];                 // conflict-free: consecutive per warp
        float aj = __fmul_rn(__fsub_rn(bj.z, bj.x), __fsub_rn(bj.w, bj.y));
        float ltx = fmaxf(bi.x, bj.x), lty = fmaxf(bi.y, bj.y);
        float rbx = fminf(bi.z, bj.z), rby = fminf(bi.w, bj.w);
        float wx = fmaxf(__fsub_rn(rbx, ltx), 0.0f);
        float wy = fmaxf(__fsub_rn(rby, lty), 0.0f);
        float inter = __fmul_rn(wx, wy);
        float uni = __fsub_rn(__fadd_rn(ai, aj), inter);
        float iou = __fdiv_rn(inter, fmaxf(uni, 1e-9f));
        int pred = (iou > 0.65f);
        unsigned bal = __ballot_sync(0xFFFFFFFFu, pred);
        if (lane == 0u)
            gm32[((size_t)i * 16u + jj) * 2u + half] = bal;
        // diagonal exclusion for rowNZ
        unsigned selfmask = 0u;
        if (jj == iw && (ib >> 5) == half) selfmask = 1u << (ib & 31u);
        nzacc |= (bal & ~selfmask);
    }
    if (lane == 0u && nzacc)
        atomicOr(&g_rowNZ[iw], 1ull << ib);
}

// ---------------- K5: greedy NMS (TMA staging + parallel OR) + output -------
__global__ void __launch_bounds__(1024) k_nms(float* __restrict__ out,
                                              int keepmode) {
    extern __shared__ __align__(16) unsigned long long Ms[];   // 16384 u64 (stride 16)
    __shared__ unsigned long long mbar;
    __shared__ unsigned long long tmp[16 * 33];
    __shared__ unsigned long long keepw[16], remv[16], vmArr[16], rowNZsh[16];
    unsigned t = threadIdx.x;

    unsigned mb   = (unsigned)__cvta_generic_to_shared(&mbar);
    unsigned sdst = (unsigned)__cvta_generic_to_shared(Ms);
    if (t == 0u) {
        asm volatile("mbarrier.init.shared::cta.b64 [%0], 1;" :: "r"(mb));
        asm volatile("fence.proxy.async.shared::cta;" ::: "memory");
    }
    __syncthreads();
    if (t == 0u) {
        asm volatile("mbarrier.arrive.expect_tx.shared::cta.b64 _, [%0], %1;"
                     :: "r"(mb), "r"(131072u) : "memory");
        asm volatile("cp.async.bulk.shared::cta.global.mbarrier::complete_tx::bytes "
                     "[%0], [%1], %2, [%3];"
                     :: "r"(sdst), "l"(g_M), "r"(131072u), "r"(mb) : "memory");
    }
    if (t < 16u) {
        remv[t]    = 0ull;
        rowNZsh[t] = g_rowNZ[t];
        vmArr[t]   = (unsigned long long)g_validw[2u * t]
                   | ((unsigned long long)g_validw[2u * t + 1u] << 32);
    }
    asm volatile(
        "{\n\t.reg .pred P;\n"
        "WL%=:\n\tmbarrier.try_wait.parity.shared::cta.b64 P, [%0], %1;\n"
        "\t@P bra WD%=;\n\tbra WL%=;\nWD%=:\n\t}"
        :: "r"(mb), "r"(0u) : "memory");
    __syncthreads();

    unsigned w = t >> 5, lane = t & 31u;
    unsigned c2 = lane & 15u, half = lane >> 4;

    for (unsigned g = 0; g < 16u; g++) {
        if (t < 32u) {
            unsigned long long vmb = vmArr[g], rvb = remv[g], nzb = rowNZsh[g];
            unsigned long long avail = vmb & ~rvb;
            unsigned long long keepmask = avail & ~nzb;
            unsigned long long serialm = avail & nzb;
            unsigned rowbase = g * 64u;
            if (serialm) {
                #pragma unroll
                for (int q = 0; q < 4; q++) {
                    if (!((serialm >> (q * 16)) & 0xFFFFull)) continue;
                    unsigned long long col[16];
                    #pragma unroll
                    for (int jj = 0; jj < 16; jj++)
                        col[jj] = Ms[(size_t)(rowbase + (unsigned)(q * 16 + jj)) * 16u + g];
                    #pragma unroll
                    for (int jj = 0; jj < 16; jj++) {
                        int j = q * 16 + jj;
                        if ((serialm >> j) & 1ull) {
                            unsigned long long below = (1ull << j) - 1ull;
                            if ((keepmask & col[jj] & below) == 0ull)
                                keepmask |= 1ull << j;
                        }
                    }
                }
            }
            if (t == 0u) keepw[g] = keepmask;
        }
        __syncthreads();
        {   // parallel cross-group OR: warp w -> rows 2w,2w+1; lane -> (half,col)
            unsigned long long km = keepw[g];
            unsigned j = 2u * w + half;
            unsigned long long acc = ((km >> j) & 1ull)
                                   ? Ms[(size_t)(g * 64u + j) * 16u + c2] : 0ull;
            acc |= __shfl_xor_sync(0xFFFFFFFFu, acc, 16);
            if (half == 0u) tmp[c2 * 33u + w] = acc;
        }
        __syncthreads();
        if (t < 512u) {
            unsigned cc = t >> 5, l = t & 31u;
            unsigned long long v = tmp[cc * 33u + l];
            #pragma unroll
            for (int off = 16; off; off >>= 1)
                v |= __shfl_xor_sync(0xFFFFFFFFu, v, off);
            if (l == 0u) remv[cc] |= v;
        }
        __syncthreads();
    }

    // output
    {
        unsigned slot = t;
        int keep = (int)((keepw[slot >> 6] >> (slot & 63u)) & 1ull);
        float m = keep ? 1.0f : 0.0f;
        float4 b = g_boxes[slot];
        float4 inf = g_info[slot];
        float* o = out + (size_t)slot * 7;
        o[0] = __fmul_rn(b.x, m);  o[1] = __fmul_rn(b.y, m);
        o[2] = __fmul_rn(b.z, m);  o[3] = __fmul_rn(b.w, m);
        o[4] = __fmul_rn(inf.x, m); o[5] = __fmul_rn(inf.y, m);
        o[6] = __fmul_rn(inf.z, m);
        if (keepmode == 0)
            out[KTOP * 7 + slot] = m;
        else
            ((unsigned char*)(out + KTOP * 7))[slot] = (unsigned char)keep;
    }

    if (t < 16u) g_rowNZ[t] = 0ull;
}

// ---------------- host ----------------
extern "C" void kernel_launch(void* const* d_in, const int* in_sizes, int n_in,
                              void* d_out, int out_size) {
    const float* pred = (const float*)d_in[0];
    float* out = (float*)d_out;
    int keepmode = 0;
    if (out_size == KTOP * 7 + KTOP / 4) keepmode = 1;

    k_score<<<NROWS / (TILES * TROWS), 256>>>(pred);      // 1
    k_sel<<<1, 1024>>>();                                 // 2
    k_gather<<<32, 256>>>(pred);                          // 3
    k_iou<<<64, 1024>>>();                                // 4 <- ncu capture slot
    cudaFuncSetAttribute(k_nms, cudaFuncAttributeMaxDynamicSharedMemorySize,
                         131072);
    k_nms<<<1, 1024, 131072>>>(out, keepmode);            // 5
}